// round 1
// baseline (speedup 1.0000x reference)
#include <cuda_runtime.h>
#include <math.h>

#define B 8
#define H 8
#define T 8192
#define DH 64
#define BKT 128
#define BSZ 64
#define BH 64
#define HH 4
#define SCALE 0.04419417382415922f   /* (h*dh=512)^-0.5 */
#define NEG 3.402823466e38f
#define KS 68                        /* padded smem row stride (floats) */

/* scratch (no allocation allowed) */
__device__ float g_x[BH * BKT * 128];   /* [bh][u][2*dh] sort-net features */
__device__ int   g_idx[BH * BKT];       /* routed source bucket (0 = null) */
__device__ float g_w[BH * BKT];         /* routing weight */

/* ------------------------------------------------------------------ */
/* Stage A: per-bucket prefix stats of rotated K                       */
/* x[bh][u][0:64]  = cumavg of kf up to token u*64 (inclusive)         */
/* x[bh][u][64:128]= kf at token u*64                                  */
/* ------------------------------------------------------------------ */
__global__ void sc_stageA(const float* __restrict__ k) {
    int bh = blockIdx.x;
    bool rot = (bh & 7) >= HH;
    __shared__ float P[BKT][DH];
    int tid = threadIdx.x;               /* 512 threads */
    int d = tid & 63, ub = tid >> 6;
    const float* kb = k + (size_t)bh * T * DH;
    for (int it = 0; it < 16; ++it) {
        int u = it * 8 + ub;
        int t0 = u * BSZ;
        float s = 0.f;
#pragma unroll 4
        for (int j = 0; j < BSZ; ++j) {
            int tt = t0 + j;
            int rt = rot ? ((tt + 63) & (T - 1)) : tt;
            s += kb[(size_t)rt * DH + d];
        }
        P[u][d] = s;
    }
    __syncthreads();
    if (tid < DH) {
        float run = 0.f;
        float* xb = g_x + (size_t)bh * BKT * 128;
        for (int u = 0; u < BKT; ++u) {
            int tt = u * BSZ;
            int rt = rot ? ((tt + 63) & (T - 1)) : tt;
            float kf = kb[(size_t)rt * DH + tid];
            xb[u * 128 + tid]      = (run + kf) / (float)(tt + 1);
            xb[u * 128 + DH + tid] = kf;
            run += P[u][tid];
        }
    }
}

/* ------------------------------------------------------------------ */
/* Stage B: sort-net logits -> masked softmax -> top-1 (idx, weight)   */
/* one warp per query bucket; W[h] cached in dynamic smem              */
/* ------------------------------------------------------------------ */
__global__ void sc_stageB(const float* __restrict__ sortW) {
    extern __shared__ float sm[];
    float* Ws = sm;                  /* 128*129 */
    float* xr = sm + 128 * 129;      /* 8*128   */
    int bh = blockIdx.y;
    int h = bh & 7;
    int tid = threadIdx.x;           /* 256 */
    const float* Wh = sortW + (size_t)h * 128 * 129;
    for (int i = tid; i < 128 * 129; i += 256) Ws[i] = Wh[i];
    __syncthreads();
    int warp = tid >> 5, lane = tid & 31;
    const float* xb = g_x + (size_t)bh * BKT * 128;
    for (int it = 0; it < 8; ++it) {
        int u = blockIdx.x * 64 + it * 8 + warp;
        float4 x4 = ((const float4*)(xb + u * 128))[lane];
        xr[warp * 128 + lane * 4 + 0] = x4.x;
        xr[warp * 128 + lane * 4 + 1] = x4.y;
        xr[warp * 128 + lane * 4 + 2] = x4.z;
        xr[warp * 128 + lane * 4 + 3] = x4.w;
        __syncwarp();
        float v[5];
#pragma unroll
        for (int g = 0; g < 5; ++g) {
            int c = lane + 32 * g;
            float acc = -NEG;
            if (c <= u) {            /* cols <= u survive the pre-softmax mask */
                float a = 0.f;
#pragma unroll 4
                for (int d = 0; d < 128; ++d) a += xr[warp * 128 + d] * Ws[d * 129 + c];
                acc = a >= 0.f ? a : 0.01f * a;   /* leaky_relu */
            }
            v[g] = acc;
        }
        float m = v[0];
#pragma unroll
        for (int g = 1; g < 5; ++g) m = fmaxf(m, v[g]);
        for (int off = 16; off >= 1; off >>= 1)
            m = fmaxf(m, __shfl_xor_sync(0xffffffffu, m, off));
        float s = 0.f;
#pragma unroll
        for (int g = 0; g < 5; ++g) s += __expf(v[g] - m);   /* masked -> exp(-huge)=0 */
        for (int off = 16; off >= 1; off >>= 1)
            s += __shfl_xor_sync(0xffffffffu, s, off);
        float bv = -NEG; int bi = 0;
#pragma unroll
        for (int g = 0; g < 5; ++g) {
            int c = lane + 32 * g;
            if (c < u && v[g] > bv) { bv = v[g]; bi = c; }   /* winner: cols < u */
        }
        for (int off = 16; off >= 1; off >>= 1) {
            float ov = __shfl_xor_sync(0xffffffffu, bv, off);
            int   oi = __shfl_xor_sync(0xffffffffu, bi, off);
            if (ov > bv || (ov == bv && oi < bi)) { bv = ov; bi = oi; }
        }
        if (lane == 0) {
            float w = 0.f; int idx = 0;
            if (u > 0 && bv > -NEG) { w = __expf(bv - m) / s; idx = bi; }
            g_w[bh * BKT + u]   = w;
            g_idx[bh * BKT + u] = idx;
        }
        __syncwarp();
    }
}

/* ------------------------------------------------------------------ */
/* Stage C: per-(bh,bucket) 64x128x64 attention tile                   */
/* ------------------------------------------------------------------ */
__global__ void __launch_bounds__(256, 2) sc_stageC(
    const float* __restrict__ q, const float* __restrict__ k,
    const float* __restrict__ v, const float* __restrict__ nk,
    const float* __restrict__ nv, float* __restrict__ out) {
    extern __shared__ float sm[];
    float* Qs = sm;                  /* [64][KS]  */
    float* K2 = sm + 64 * KS;        /* [128][KS] */
    float* V2 = K2 + 128 * KS;       /* [128][KS] */
    float* Ps = K2;                  /* probs reuse K2 region after S */

    int u = blockIdx.x, bh = blockIdx.y;
    int h = bh & 7;
    bool rot = h >= HH;
    int tid = threadIdx.x;           /* 256 */
    int t0 = u * BSZ;
    const float* qb = q + (size_t)bh * T * DH;
    const float* kb = k + (size_t)bh * T * DH;
    const float* vb = v + (size_t)bh * T * DH;

    int   ridx = g_idx[bh * BKT + u];
    float rw   = g_w[bh * BKT + u];

    /* cooperative load: Q, local K/V (rows 64..127), routed K/V * w (rows 0..63) */
#pragma unroll
    for (int it = 0; it < 4; ++it) {
        int i = tid + 256 * it;
        int row = i >> 4, ch = i & 15;
        int tt = t0 + row;
        int rt = rot ? ((tt + 63) & (T - 1)) : tt;
        float4 q4 = *(const float4*)(qb + (size_t)rt * DH + ch * 4);
        *(float4*)(Qs + row * KS + ch * 4) = q4;
        float4 k4 = *(const float4*)(kb + (size_t)rt * DH + ch * 4);
        *(float4*)(K2 + (64 + row) * KS + ch * 4) = k4;
        float4 v4 = *(const float4*)(vb + (size_t)rt * DH + ch * 4);
        *(float4*)(V2 + (64 + row) * KS + ch * 4) = v4;
        float4 rk, rv;
        if (ridx == 0) {
            rk = *(const float4*)(nk + h * DH + ch * 4);
            rv = *(const float4*)(nv + h * DH + ch * 4);
        } else {
            int st = (ridx - 1) * BSZ + row;
            int srt = rot ? ((st + 63) & (T - 1)) : st;
            rk = *(const float4*)(kb + (size_t)srt * DH + ch * 4);
            rv = *(const float4*)(vb + (size_t)srt * DH + ch * 4);
        }
        rk.x *= rw; rk.y *= rw; rk.z *= rw; rk.w *= rw;
        rv.x *= rw; rv.y *= rw; rv.z *= rw; rv.w *= rw;
        *(float4*)(K2 + row * KS + ch * 4) = rk;
        *(float4*)(V2 + row * KS + ch * 4) = rv;
    }
    __syncthreads();

    /* S = Q K2^T : thread (ty,tx) -> rows 4ty..+3, cols tx+16j (j<8) */
    int ty = tid >> 4, tx = tid & 15;
    float acc[4][8];
#pragma unroll
    for (int i = 0; i < 4; ++i)
#pragma unroll
        for (int j = 0; j < 8; ++j) acc[i][j] = 0.f;

    for (int kk = 0; kk < DH; kk += 4) {
        float4 q4[4];
#pragma unroll
        for (int i = 0; i < 4; ++i) q4[i] = *(const float4*)(Qs + (4 * ty + i) * KS + kk);
#pragma unroll
        for (int j = 0; j < 8; ++j) {
            float4 k4 = *(const float4*)(K2 + (tx + 16 * j) * KS + kk);
#pragma unroll
            for (int i = 0; i < 4; ++i)
                acc[i][j] += q4[i].x * k4.x + q4[i].y * k4.y + q4[i].z * k4.z + q4[i].w * k4.w;
        }
    }

    /* scale + mask */
    bool special = rot && (u == BKT - 1);
#pragma unroll
    for (int i = 0; i < 4; ++i) {
        int r = 4 * ty + i;
#pragma unroll
        for (int j = 0; j < 8; ++j) {
            int c = tx + 16 * j;
            bool ok = (c < BSZ) || (c - BSZ <= r);
            if (special && r >= 1 && c <= BSZ) ok = false;
            acc[i][j] = ok ? acc[i][j] * SCALE : -NEG;
        }
    }

    /* row softmax across the 16 tx-lanes */
    float rs[4];
#pragma unroll
    for (int i = 0; i < 4; ++i) {
        float m = acc[i][0];
#pragma unroll
        for (int j = 1; j < 8; ++j) m = fmaxf(m, acc[i][j]);
#pragma unroll
        for (int off = 8; off >= 1; off >>= 1)
            m = fmaxf(m, __shfl_xor_sync(0xffffffffu, m, off));
        float s = 0.f;
#pragma unroll
        for (int j = 0; j < 8; ++j) { float p = __expf(acc[i][j] - m); acc[i][j] = p; s += p; }
#pragma unroll
        for (int off = 8; off >= 1; off >>= 1)
            s += __shfl_xor_sync(0xffffffffu, s, off);
        rs[i] = 1.f / s;
    }

    __syncthreads();                 /* everyone done reading K2 */
#pragma unroll
    for (int i = 0; i < 4; ++i)
#pragma unroll
        for (int j = 0; j < 8; ++j)
            Ps[(4 * ty + i) * 128 + (tx + 16 * j)] = acc[i][j] * rs[i];
    __syncthreads();

    /* O = P V2 : thread -> rows 4ty..+3, d-cols 4tx..+3 */
    float o[4][4];
#pragma unroll
    for (int i = 0; i < 4; ++i)
#pragma unroll
        for (int j = 0; j < 4; ++j) o[i][j] = 0.f;

    for (int key = 0; key < 128; key += 4) {
        float pr[4][4];
#pragma unroll
        for (int i = 0; i < 4; ++i) {
            float4 p4 = *(const float4*)(Ps + (4 * ty + i) * 128 + key);
            pr[i][0] = p4.x; pr[i][1] = p4.y; pr[i][2] = p4.z; pr[i][3] = p4.w;
        }
#pragma unroll
        for (int kk2 = 0; kk2 < 4; ++kk2) {
            float4 v4 = *(const float4*)(V2 + (key + kk2) * KS + 4 * tx);
#pragma unroll
            for (int i = 0; i < 4; ++i) {
                o[i][0] += pr[i][kk2] * v4.x;
                o[i][1] += pr[i][kk2] * v4.y;
                o[i][2] += pr[i][kk2] * v4.z;
                o[i][3] += pr[i][kk2] * v4.w;
            }
        }
    }

    /* store with inverse head rotation (same bijection as load) */
#pragma unroll
    for (int i = 0; i < 4; ++i) {
        int r = 4 * ty + i;
        int tt = t0 + r;
        int rt = rot ? ((tt + 63) & (T - 1)) : tt;
        *(float4*)(out + ((size_t)bh * T + rt) * DH + 4 * tx) =
            make_float4(o[i][0], o[i][1], o[i][2], o[i][3]);
    }
}

extern "C" void kernel_launch(void* const* d_in, const int* in_sizes, int n_in,
                              void* d_out, int out_size) {
    const float* q  = (const float*)d_in[0];
    const float* k  = (const float*)d_in[1];
    const float* v  = (const float*)d_in[2];
    const float* sW = (const float*)d_in[3];
    const float* nk = (const float*)d_in[4];
    const float* nv = (const float*)d_in[5];
    float* out = (float*)d_out;

    int smemB = (128 * 129 + 8 * 128) * 4;        /* 70144 B */
    int smemC = (64 + 128 + 128) * KS * 4;        /* 87040 B */
    cudaFuncSetAttribute(sc_stageB, cudaFuncAttributeMaxDynamicSharedMemorySize, smemB);
    cudaFuncSetAttribute(sc_stageC, cudaFuncAttributeMaxDynamicSharedMemorySize, smemC);

    sc_stageA<<<BH, 512>>>(k);
    sc_stageB<<<dim3(2, BH), 256, smemB>>>(sW);
    sc_stageC<<<dim3(BKT, BH), 256, smemC>>>(q, k, v, nk, nv, out);
}

// round 2
// speedup vs baseline: 1.2531x; 1.2531x over previous
#include <cuda_runtime.h>
#include <math.h>

#define B 8
#define H 8
#define T 8192
#define DH 64
#define BKT 128
#define BSZ 64
#define BH 64
#define HH 4
#define SCALE 0.04419417382415922f   /* (h*dh=512)^-0.5 */
#define NEG 3.402823466e38f
#define KS 68                        /* padded smem row stride (floats) */

/* scratch (no allocation allowed) */
__device__ float g_x[BH * BKT * 128];   /* [bh][u][2*dh] sort-net features */
__device__ float g_ps[BH * BKT * DH];   /* per-bucket partial sums of rotated K */
__device__ int   g_idx[BH * BKT];       /* routed source bucket (0 = null) */
__device__ float g_w[BH * BKT];         /* routing weight */

/* ---- packed f32x2 helpers (sm_103a) ---- */
__device__ __forceinline__ unsigned long long bcast2(float a) {
    unsigned long long r;
    asm("mov.b64 %0, {%1, %1};" : "=l"(r) : "f"(a));
    return r;
}
__device__ __forceinline__ void fma2(unsigned long long& d,
                                     unsigned long long a, unsigned long long b) {
    asm("fma.rn.f32x2 %0, %1, %2, %0;" : "+l"(d) : "l"(a), "l"(b));
}
__device__ __forceinline__ float2 unpack2(unsigned long long a) {
    float2 f;
    asm("mov.b64 {%0, %1}, %2;" : "=f"(f.x), "=f"(f.y) : "l"(a));
    return f;
}

/* ------------------------------------------------------------------ */
/* Stage A1: per-bucket sums of rotated K — one CTA per (bucket, bh)  */
/* ------------------------------------------------------------------ */
__global__ void sc_stageA1(const float* __restrict__ k) {
    int u = blockIdx.x, bh = blockIdx.y;
    bool rot = (bh & 7) >= HH;
    __shared__ float P[4][DH];
    int tid = threadIdx.x;               /* 256 */
    int d = tid & 63, part = tid >> 6;
    const float* kb = k + (size_t)bh * T * DH;
    int t0 = u * BSZ + part * 16;
    float s = 0.f;
#pragma unroll
    for (int j = 0; j < 16; ++j) {
        int tt = t0 + j;
        int rt = rot ? ((tt + 63) & (T - 1)) : tt;
        s += kb[(size_t)rt * DH + d];
    }
    P[part][d] = s;
    __syncthreads();
    if (part == 0)
        g_ps[((size_t)bh * BKT + u) * DH + d] = P[0][d] + P[1][d] + P[2][d] + P[3][d];
}

/* ------------------------------------------------------------------ */
/* Stage A2: prefix over buckets -> sort-net features g_x             */
/* ------------------------------------------------------------------ */
__global__ void sc_stageA2(const float* __restrict__ k) {
    int bh = blockIdx.x;
    bool rot = (bh & 7) >= HH;
    int d = threadIdx.x;                 /* 64 */
    const float* kb = k + (size_t)bh * T * DH;
    const float* ps = g_ps + (size_t)bh * BKT * DH;
    float* xb = g_x + (size_t)bh * BKT * 128;
    float run = 0.f;
#pragma unroll 8
    for (int u = 0; u < BKT; ++u) {
        int tt = u * BSZ;
        int rt = rot ? ((tt + 63) & (T - 1)) : tt;
        float kf = kb[(size_t)rt * DH + d];
        xb[u * 128 + d]      = (run + kf) / (float)(tt + 1);
        xb[u * 128 + DH + d] = kf;
        run += ps[u * DH + d];
    }
}

/* ------------------------------------------------------------------ */
/* Stage B: sort-net logits -> masked softmax -> top-1 (idx, weight)   */
/* ------------------------------------------------------------------ */
__global__ void sc_stageB(const float* __restrict__ sortW) {
    extern __shared__ float sm[];
    float* Ws = sm;                  /* 128*129 */
    float* xr = sm + 128 * 129;      /* 8*128   */
    int bh = blockIdx.y;
    int h = bh & 7;
    int tid = threadIdx.x;           /* 256 */
    const float* Wh = sortW + (size_t)h * 128 * 129;
    for (int i = tid; i < 128 * 129; i += 256) Ws[i] = Wh[i];
    __syncthreads();
    int warp = tid >> 5, lane = tid & 31;
    const float* xb = g_x + (size_t)bh * BKT * 128;
    for (int it = 0; it < 8; ++it) {
        int u = blockIdx.x * 64 + it * 8 + warp;
        float4 x4 = ((const float4*)(xb + u * 128))[lane];
        xr[warp * 128 + lane * 4 + 0] = x4.x;
        xr[warp * 128 + lane * 4 + 1] = x4.y;
        xr[warp * 128 + lane * 4 + 2] = x4.z;
        xr[warp * 128 + lane * 4 + 3] = x4.w;
        __syncwarp();
        float v[5];
#pragma unroll
        for (int g = 0; g < 5; ++g) {
            int c = lane + 32 * g;
            float acc = -NEG;
            if (c <= u) {
                float a = 0.f;
#pragma unroll 4
                for (int d = 0; d < 128; ++d) a += xr[warp * 128 + d] * Ws[d * 129 + c];
                acc = a >= 0.f ? a : 0.01f * a;   /* leaky_relu */
            }
            v[g] = acc;
        }
        float m = v[0];
#pragma unroll
        for (int g = 1; g < 5; ++g) m = fmaxf(m, v[g]);
        for (int off = 16; off >= 1; off >>= 1)
            m = fmaxf(m, __shfl_xor_sync(0xffffffffu, m, off));
        float s = 0.f;
#pragma unroll
        for (int g = 0; g < 5; ++g) s += __expf(v[g] - m);
        for (int off = 16; off >= 1; off >>= 1)
            s += __shfl_xor_sync(0xffffffffu, s, off);
        float bv = -NEG; int bi = 0;
#pragma unroll
        for (int g = 0; g < 5; ++g) {
            int c = lane + 32 * g;
            if (c < u && v[g] > bv) { bv = v[g]; bi = c; }
        }
        for (int off = 16; off >= 1; off >>= 1) {
            float ov = __shfl_xor_sync(0xffffffffu, bv, off);
            int   oi = __shfl_xor_sync(0xffffffffu, bi, off);
            if (ov > bv || (ov == bv && oi < bi)) { bv = ov; bi = oi; }
        }
        if (lane == 0) {
            float w = 0.f; int idx = 0;
            if (u > 0 && bv > -NEG) { w = __expf(bv - m) / s; idx = bi; }
            g_w[bh * BKT + u]   = w;
            g_idx[bh * BKT + u] = idx;
        }
        __syncwarp();
    }
}

/* ------------------------------------------------------------------ */
/* Stage C: per-(bh,bucket) 64x128x64 attention tile, packed f32x2    */
/* ------------------------------------------------------------------ */
__global__ void __launch_bounds__(256, 2) sc_stageC(
    const float* __restrict__ q, const float* __restrict__ k,
    const float* __restrict__ v, const float* __restrict__ nk,
    const float* __restrict__ nv, float* __restrict__ out) {
    extern __shared__ float sm[];
    float* Qs = sm;                  /* [64][KS]  */
    float* K2 = sm + 64 * KS;        /* [128][KS] */
    float* V2 = K2 + 128 * KS;       /* [128][KS] */
    float* Ps = K2;                  /* probs reuse K2 region after S */

    int u = blockIdx.x, bh = blockIdx.y;
    int h = bh & 7;
    bool rot = h >= HH;
    int tid = threadIdx.x;           /* 256 */
    int t0 = u * BSZ;
    const float* qb = q + (size_t)bh * T * DH;
    const float* kb = k + (size_t)bh * T * DH;
    const float* vb = v + (size_t)bh * T * DH;

    int   ridx = g_idx[bh * BKT + u];
    float rw   = g_w[bh * BKT + u];

    /* cooperative load: Q, local K/V (rows 64..127), routed K/V * w (rows 0..63) */
#pragma unroll
    for (int it = 0; it < 4; ++it) {
        int i = tid + 256 * it;
        int row = i >> 4, ch = i & 15;
        int tt = t0 + row;
        int rt = rot ? ((tt + 63) & (T - 1)) : tt;
        float4 q4 = *(const float4*)(qb + (size_t)rt * DH + ch * 4);
        *(float4*)(Qs + row * KS + ch * 4) = q4;
        float4 k4 = *(const float4*)(kb + (size_t)rt * DH + ch * 4);
        *(float4*)(K2 + (64 + row) * KS + ch * 4) = k4;
        float4 v4 = *(const float4*)(vb + (size_t)rt * DH + ch * 4);
        *(float4*)(V2 + (64 + row) * KS + ch * 4) = v4;
        float4 rk, rv;
        if (ridx == 0) {
            rk = *(const float4*)(nk + h * DH + ch * 4);
            rv = *(const float4*)(nv + h * DH + ch * 4);
        } else {
            int st = (ridx - 1) * BSZ + row;
            int srt = rot ? ((st + 63) & (T - 1)) : st;
            rk = *(const float4*)(kb + (size_t)srt * DH + ch * 4);
            rv = *(const float4*)(vb + (size_t)srt * DH + ch * 4);
        }
        rk.x *= rw; rk.y *= rw; rk.z *= rw; rk.w *= rw;
        rv.x *= rw; rv.y *= rw; rv.z *= rw; rv.w *= rw;
        *(float4*)(K2 + row * KS + ch * 4) = rk;
        *(float4*)(V2 + row * KS + ch * 4) = rv;
    }
    __syncthreads();

    /* S = Q K2^T : thread (ty,tx) -> rows 4ty..+3, cols tx+16j (j<8) */
    int ty = tid >> 4, tx = tid & 15;
    unsigned long long acc2[4][8];
#pragma unroll
    for (int i = 0; i < 4; ++i)
#pragma unroll
        for (int j = 0; j < 8; ++j) acc2[i][j] = 0ull;

    for (int kk = 0; kk < DH; kk += 4) {
        ulonglong2 q2[4];
#pragma unroll
        for (int i = 0; i < 4; ++i)
            q2[i] = *(const ulonglong2*)(Qs + (4 * ty + i) * KS + kk);
#pragma unroll
        for (int j = 0; j < 8; ++j) {
            ulonglong2 k2 = *(const ulonglong2*)(K2 + (tx + 16 * j) * KS + kk);
#pragma unroll
            for (int i = 0; i < 4; ++i) {
                fma2(acc2[i][j], q2[i].x, k2.x);
                fma2(acc2[i][j], q2[i].y, k2.y);
            }
        }
    }

    /* reduce packed halves, scale + mask */
    float acc[4][8];
    bool special = rot && (u == BKT - 1);
#pragma unroll
    for (int i = 0; i < 4; ++i) {
        int r = 4 * ty + i;
#pragma unroll
        for (int j = 0; j < 8; ++j) {
            float2 p = unpack2(acc2[i][j]);
            float a = p.x + p.y;
            int c = tx + 16 * j;
            bool ok = (c < BSZ) || (c - BSZ <= r);
            if (special && r >= 1 && c <= BSZ) ok = false;
            acc[i][j] = ok ? a * SCALE : -NEG;
        }
    }

    /* row softmax across the 16 tx-lanes */
    float rs[4];
#pragma unroll
    for (int i = 0; i < 4; ++i) {
        float m = acc[i][0];
#pragma unroll
        for (int j = 1; j < 8; ++j) m = fmaxf(m, acc[i][j]);
#pragma unroll
        for (int off = 8; off >= 1; off >>= 1)
            m = fmaxf(m, __shfl_xor_sync(0xffffffffu, m, off));
        float s = 0.f;
#pragma unroll
        for (int j = 0; j < 8; ++j) { float p = __expf(acc[i][j] - m); acc[i][j] = p; s += p; }
#pragma unroll
        for (int off = 8; off >= 1; off >>= 1)
            s += __shfl_xor_sync(0xffffffffu, s, off);
        rs[i] = 1.f / s;
    }

    __syncthreads();                 /* everyone done reading K2 */
#pragma unroll
    for (int i = 0; i < 4; ++i)
#pragma unroll
        for (int j = 0; j < 8; ++j)
            Ps[(4 * ty + i) * 128 + (tx + 16 * j)] = acc[i][j] * rs[i];
    __syncthreads();

    /* O = P V2 : thread -> rows 4ty..+3, d-cols 4tx..+3 (2 packed pairs) */
    unsigned long long o2[4][2];
#pragma unroll
    for (int i = 0; i < 4; ++i) { o2[i][0] = 0ull; o2[i][1] = 0ull; }

    for (int key = 0; key < 128; key += 4) {
        float pr[4][4];
#pragma unroll
        for (int i = 0; i < 4; ++i) {
            float4 p4 = *(const float4*)(Ps + (4 * ty + i) * 128 + key);
            pr[i][0] = p4.x; pr[i][1] = p4.y; pr[i][2] = p4.z; pr[i][3] = p4.w;
        }
#pragma unroll
        for (int kk2 = 0; kk2 < 4; ++kk2) {
            ulonglong2 v2 = *(const ulonglong2*)(V2 + (key + kk2) * KS + 4 * tx);
#pragma unroll
            for (int i = 0; i < 4; ++i) {
                unsigned long long p2 = bcast2(pr[i][kk2]);
                fma2(o2[i][0], p2, v2.x);
                fma2(o2[i][1], p2, v2.y);
            }
        }
    }

    /* store with inverse head rotation (same bijection as load) */
#pragma unroll
    for (int i = 0; i < 4; ++i) {
        int r = 4 * ty + i;
        int tt = t0 + r;
        int rt = rot ? ((tt + 63) & (T - 1)) : tt;
        float2 p0 = unpack2(o2[i][0]);
        float2 p1 = unpack2(o2[i][1]);
        *(float4*)(out + ((size_t)bh * T + rt) * DH + 4 * tx) =
            make_float4(p0.x, p0.y, p1.x, p1.y);
    }
}

extern "C" void kernel_launch(void* const* d_in, const int* in_sizes, int n_in,
                              void* d_out, int out_size) {
    const float* q  = (const float*)d_in[0];
    const float* k  = (const float*)d_in[1];
    const float* v  = (const float*)d_in[2];
    const float* sW = (const float*)d_in[3];
    const float* nk = (const float*)d_in[4];
    const float* nv = (const float*)d_in[5];
    float* out = (float*)d_out;

    int smemB = (128 * 129 + 8 * 128) * 4;        /* 70144 B */
    int smemC = (64 + 128 + 128) * KS * 4;        /* 87040 B */
    cudaFuncSetAttribute(sc_stageB, cudaFuncAttributeMaxDynamicSharedMemorySize, smemB);
    cudaFuncSetAttribute(sc_stageC, cudaFuncAttributeMaxDynamicSharedMemorySize, smemC);

    sc_stageA1<<<dim3(BKT, BH), 256>>>(k);
    sc_stageA2<<<BH, DH>>>(k);
    sc_stageB<<<dim3(2, BH), 256, smemB>>>(sW);
    sc_stageC<<<dim3(BKT, BH), 256, smemC>>>(q, k, v, nk, nv, out);
}

// round 7
// speedup vs baseline: 2.0758x; 1.6566x over previous
#include <cuda_runtime.h>
#include <math.h>
#include <stdint.h>

#define B 8
#define H 8
#define T 8192
#define DH 64
#define BKT 128
#define BSZ 64
#define BH 64
#define HH 4
#define SCALE 0.04419417382415922f   /* (h*dh=512)^-0.5 */
#define NEG 3.402823466e38f
#define KSQ 68    /* Qs/K2 stride (floats): bank stride 4 -> conflict-free A/B frags */
#define KSV 72    /* V2 stride: bank stride 8 -> conflict-free PV B frags */
#define PSD 132   /* Ps stride: bank stride 4 -> conflict-free PV A frags */

/* scratch (no allocation allowed) */
__device__ float g_x[BH * BKT * 128];
__device__ float g_ps[BH * BKT * DH];
__device__ int   g_idx[BH * BKT];
__device__ float g_w[BH * BKT];

__device__ __forceinline__ uint32_t f2tf32(float f) {
    uint32_t u;
    asm("cvt.rna.tf32.f32 %0, %1;" : "=r"(u) : "f"(f));
    return u;
}
__device__ __forceinline__ float tf32f(float f) {
    return __uint_as_float(f2tf32(f));
}
__device__ __forceinline__ void mma_tf32(float d[4], uint32_t a0, uint32_t a1,
                                         uint32_t a2, uint32_t a3,
                                         uint32_t b0, uint32_t b1) {
    asm("mma.sync.aligned.m16n8k8.row.col.f32.tf32.tf32.f32 "
        "{%0,%1,%2,%3}, {%4,%5,%6,%7}, {%8,%9}, {%0,%1,%2,%3};"
        : "+f"(d[0]), "+f"(d[1]), "+f"(d[2]), "+f"(d[3])
        : "r"(a0), "r"(a1), "r"(a2), "r"(a3), "r"(b0), "r"(b1));
}

/* ------------------------------------------------------------------ */
__global__ void sc_stageA1(const float* __restrict__ k) {
    int u = blockIdx.x, bh = blockIdx.y;
    bool rot = (bh & 7) >= HH;
    __shared__ float P[4][DH];
    int tid = threadIdx.x;
    int d = tid & 63, part = tid >> 6;
    const float* kb = k + (size_t)bh * T * DH;
    int t0 = u * BSZ + part * 16;
    float s = 0.f;
#pragma unroll
    for (int j = 0; j < 16; ++j) {
        int tt = t0 + j;
        int rt = rot ? ((tt + 63) & (T - 1)) : tt;
        s += kb[(size_t)rt * DH + d];
    }
    P[part][d] = s;
    __syncthreads();
    if (part == 0)
        g_ps[((size_t)bh * BKT + u) * DH + d] = P[0][d] + P[1][d] + P[2][d] + P[3][d];
}

__global__ void sc_stageA2(const float* __restrict__ k) {
    int bh = blockIdx.x;
    bool rot = (bh & 7) >= HH;
    int d = threadIdx.x;
    const float* kb = k + (size_t)bh * T * DH;
    const float* ps = g_ps + (size_t)bh * BKT * DH;
    float* xb = g_x + (size_t)bh * BKT * 128;
    float run = 0.f;
#pragma unroll 8
    for (int u = 0; u < BKT; ++u) {
        int tt = u * BSZ;
        int rt = rot ? ((tt + 63) & (T - 1)) : tt;
        float kf = kb[(size_t)rt * DH + d];
        xb[u * 128 + d]      = (run + kf) / (float)(tt + 1);
        xb[u * 128 + DH + d] = kf;
        run += ps[u * DH + d];
    }
}

/* ------------------------------------------------------------------ */
__global__ void sc_stageB(const float* __restrict__ sortW) {
    extern __shared__ float sm[];
    float* Ws = sm;
    float* xr = sm + 128 * 129;
    int bh = blockIdx.y;
    int h = bh & 7;
    int tid = threadIdx.x;
    const float* Wh = sortW + (size_t)h * 128 * 129;
    for (int i = tid; i < 128 * 129; i += 256) Ws[i] = Wh[i];
    __syncthreads();
    int warp = tid >> 5, lane = tid & 31;
    const float* xb = g_x + (size_t)bh * BKT * 128;
    for (int it = 0; it < 8; ++it) {
        int u = blockIdx.x * 64 + it * 8 + warp;
        float4 x4 = ((const float4*)(xb + u * 128))[lane];
        xr[warp * 128 + lane * 4 + 0] = x4.x;
        xr[warp * 128 + lane * 4 + 1] = x4.y;
        xr[warp * 128 + lane * 4 + 2] = x4.z;
        xr[warp * 128 + lane * 4 + 3] = x4.w;
        __syncwarp();
        float v[5];
#pragma unroll
        for (int g = 0; g < 5; ++g) {
            int c = lane + 32 * g;
            float acc = -NEG;
            if (c <= u) {
                float a = 0.f;
#pragma unroll 4
                for (int d = 0; d < 128; ++d) a += xr[warp * 128 + d] * Ws[d * 129 + c];
                acc = a >= 0.f ? a : 0.01f * a;
            }
            v[g] = acc;
        }
        float m = v[0];
#pragma unroll
        for (int g = 1; g < 5; ++g) m = fmaxf(m, v[g]);
        for (int off = 16; off >= 1; off >>= 1)
            m = fmaxf(m, __shfl_xor_sync(0xffffffffu, m, off));
        float s = 0.f;
#pragma unroll
        for (int g = 0; g < 5; ++g) s += __expf(v[g] - m);
        for (int off = 16; off >= 1; off >>= 1)
            s += __shfl_xor_sync(0xffffffffu, s, off);
        float bv = -NEG; int bi = 0;
#pragma unroll
        for (int g = 0; g < 5; ++g) {
            int c = lane + 32 * g;
            if (c < u && v[g] > bv) { bv = v[g]; bi = c; }
        }
        for (int off = 16; off >= 1; off >>= 1) {
            float ov = __shfl_xor_sync(0xffffffffu, bv, off);
            int   oi = __shfl_xor_sync(0xffffffffu, bi, off);
            if (ov > bv || (ov == bv && oi < bi)) { bv = ov; bi = oi; }
        }
        if (lane == 0) {
            float w = 0.f; int idx = 0;
            if (u > 0 && bv > -NEG) { w = __expf(bv - m) / s; idx = bi; }
            g_w[bh * BKT + u]   = w;
            g_idx[bh * BKT + u] = idx;
        }
        __syncwarp();
    }
}

/* ------------------------------------------------------------------ */
/* Stage C: 64x128x64 attention tile via mma.sync tf32                */
/* smem: Qs[64][68] | K2[128][68] (later Ps[64][132]) | V2[128][72]   */
/*       | red[256]                                                   */
/* ------------------------------------------------------------------ */
#define SM_QS   0
#define SM_K2   (64 * KSQ)
#define SM_V2   (SM_K2 + 128 * KSQ)
#define SM_RED  (SM_V2 + 128 * KSV)
#define SM_TOT  (SM_RED + 256)

__global__ void __launch_bounds__(256, 2) sc_stageC(
    const float* __restrict__ q, const float* __restrict__ k,
    const float* __restrict__ v, const float* __restrict__ nk,
    const float* __restrict__ nv, float* __restrict__ out) {
    extern __shared__ float sm[];
    float* Qs = sm + SM_QS;
    float* K2 = sm + SM_K2;
    float* V2 = sm + SM_V2;
    float* Ps = sm + SM_K2;          /* overlay after S consumed */
    float* red = sm + SM_RED;        /* [64][2] max, then [64][2] sum */

    int u = blockIdx.x, bh = blockIdx.y;
    int h = bh & 7;
    bool rot = h >= HH;
    int tid = threadIdx.x;
    int t0 = u * BSZ;
    const float* qb = q + (size_t)bh * T * DH;
    const float* kb = k + (size_t)bh * T * DH;
    const float* vb = v + (size_t)bh * T * DH;

    int   ridx = g_idx[bh * BKT + u];
    float rw   = g_w[bh * BKT + u];

    /* cooperative load with tf32 conversion */
#pragma unroll
    for (int it = 0; it < 4; ++it) {
        int i = tid + 256 * it;
        int row = i >> 4, ch = i & 15;
        int tt = t0 + row;
        int rt = rot ? ((tt + 63) & (T - 1)) : tt;
        float4 q4 = *(const float4*)(qb + (size_t)rt * DH + ch * 4);
        Qs[row * KSQ + ch * 4 + 0] = tf32f(q4.x);
        Qs[row * KSQ + ch * 4 + 1] = tf32f(q4.y);
        Qs[row * KSQ + ch * 4 + 2] = tf32f(q4.z);
        Qs[row * KSQ + ch * 4 + 3] = tf32f(q4.w);
        float4 k4 = *(const float4*)(kb + (size_t)rt * DH + ch * 4);
        K2[(64 + row) * KSQ + ch * 4 + 0] = tf32f(k4.x);
        K2[(64 + row) * KSQ + ch * 4 + 1] = tf32f(k4.y);
        K2[(64 + row) * KSQ + ch * 4 + 2] = tf32f(k4.z);
        K2[(64 + row) * KSQ + ch * 4 + 3] = tf32f(k4.w);
        float4 v4 = *(const float4*)(vb + (size_t)rt * DH + ch * 4);
        V2[(64 + row) * KSV + ch * 4 + 0] = tf32f(v4.x);
        V2[(64 + row) * KSV + ch * 4 + 1] = tf32f(v4.y);
        V2[(64 + row) * KSV + ch * 4 + 2] = tf32f(v4.z);
        V2[(64 + row) * KSV + ch * 4 + 3] = tf32f(v4.w);
        float4 rk, rv;
        if (ridx == 0) {
            rk = *(const float4*)(nk + h * DH + ch * 4);
            rv = *(const float4*)(nv + h * DH + ch * 4);
        } else {
            int st = (ridx - 1) * BSZ + row;
            int srt = rot ? ((st + 63) & (T - 1)) : st;
            rk = *(const float4*)(kb + (size_t)srt * DH + ch * 4);
            rv = *(const float4*)(vb + (size_t)srt * DH + ch * 4);
        }
        K2[row * KSQ + ch * 4 + 0] = tf32f(rk.x * rw);
        K2[row * KSQ + ch * 4 + 1] = tf32f(rk.y * rw);
        K2[row * KSQ + ch * 4 + 2] = tf32f(rk.z * rw);
        K2[row * KSQ + ch * 4 + 3] = tf32f(rk.w * rw);
        V2[row * KSV + ch * 4 + 0] = tf32f(rv.x * rw);
        V2[row * KSV + ch * 4 + 1] = tf32f(rv.y * rw);
        V2[row * KSV + ch * 4 + 2] = tf32f(rv.z * rw);
        V2[row * KSV + ch * 4 + 3] = tf32f(rv.w * rw);
    }
    __syncthreads();

    int w  = tid >> 5, l = tid & 31;
    int wr = w & 3, wc = w >> 2;      /* 4x2 warp grid for S */
    int g  = l >> 2, lk = l & 3;      /* groupID, thread-in-group */
    int r0 = wr * 16 + g;             /* rows r0, r0+8 */

    /* ---- S = Q K2^T ---- */
    float sa[8][4];
#pragma unroll
    for (int nt = 0; nt < 8; ++nt)
#pragma unroll
        for (int j = 0; j < 4; ++j) sa[nt][j] = 0.f;

#pragma unroll
    for (int ks = 0; ks < 8; ++ks) {
        int kc = ks * 8 + lk;
        uint32_t a0 = __float_as_uint(Qs[r0 * KSQ + kc]);
        uint32_t a1 = __float_as_uint(Qs[(r0 + 8) * KSQ + kc]);
        uint32_t a2 = __float_as_uint(Qs[r0 * KSQ + kc + 4]);
        uint32_t a3 = __float_as_uint(Qs[(r0 + 8) * KSQ + kc + 4]);
#pragma unroll
        for (int nt = 0; nt < 8; ++nt) {
            int krow = wc * 64 + nt * 8 + g;
            uint32_t b0 = __float_as_uint(K2[krow * KSQ + kc]);
            uint32_t b1 = __float_as_uint(K2[krow * KSQ + kc + 4]);
            mma_tf32(sa[nt], a0, a1, a2, a3, b0, b1);
        }
    }

    /* scale + mask (rows r0/r0+8, cols wc*64 + nt*8 + 2lk + {0,1}) */
    bool special = rot && (u == BKT - 1);
#pragma unroll
    for (int nt = 0; nt < 8; ++nt) {
#pragma unroll
        for (int j = 0; j < 4; ++j) {
            int r = (j < 2) ? r0 : r0 + 8;
            int c = wc * 64 + nt * 8 + 2 * lk + (j & 1);
            bool ok = (c < BSZ) || (c - BSZ <= r);
            if (special && r >= 1 && c <= BSZ) ok = false;
            sa[nt][j] = ok ? sa[nt][j] * SCALE : -NEG;
        }
    }

    /* row max: quad reduce then cross-warp (2 col warps) via smem */
    float m0 = -NEG, m1 = -NEG;
#pragma unroll
    for (int nt = 0; nt < 8; ++nt) {
        m0 = fmaxf(m0, fmaxf(sa[nt][0], sa[nt][1]));
        m1 = fmaxf(m1, fmaxf(sa[nt][2], sa[nt][3]));
    }
#pragma unroll
    for (int off = 1; off <= 2; off <<= 1) {
        m0 = fmaxf(m0, __shfl_xor_sync(0xffffffffu, m0, off));
        m1 = fmaxf(m1, __shfl_xor_sync(0xffffffffu, m1, off));
    }
    if (lk == 0) { red[r0 * 2 + wc] = m0; red[(r0 + 8) * 2 + wc] = m1; }
    __syncthreads();
    float M0 = fmaxf(red[r0 * 2], red[r0 * 2 + 1]);
    float M1 = fmaxf(red[(r0 + 8) * 2], red[(r0 + 8) * 2 + 1]);

    float s0 = 0.f, s1 = 0.f;
#pragma unroll
    for (int nt = 0; nt < 8; ++nt) {
        sa[nt][0] = __expf(sa[nt][0] - M0); s0 += sa[nt][0];
        sa[nt][1] = __expf(sa[nt][1] - M0); s0 += sa[nt][1];
        sa[nt][2] = __expf(sa[nt][2] - M1); s1 += sa[nt][2];
        sa[nt][3] = __expf(sa[nt][3] - M1); s1 += sa[nt][3];
    }
#pragma unroll
    for (int off = 1; off <= 2; off <<= 1) {
        s0 += __shfl_xor_sync(0xffffffffu, s0, off);
        s1 += __shfl_xor_sync(0xffffffffu, s1, off);
    }
    if (lk == 0) { red[128 + r0 * 2 + wc] = s0; red[128 + (r0 + 8) * 2 + wc] = s1; }
    __syncthreads();
    float inv0 = 1.f / (red[128 + r0 * 2] + red[128 + r0 * 2 + 1]);
    float inv1 = 1.f / (red[128 + (r0 + 8) * 2] + red[128 + (r0 + 8) * 2 + 1]);

    /* store P (tf32) to smem overlay; K2 fully consumed before first sync */
#pragma unroll
    for (int nt = 0; nt < 8; ++nt) {
        int c = wc * 64 + nt * 8 + 2 * lk;
        float2 p0 = make_float2(tf32f(sa[nt][0] * inv0), tf32f(sa[nt][1] * inv0));
        float2 p1 = make_float2(tf32f(sa[nt][2] * inv1), tf32f(sa[nt][3] * inv1));
        *(float2*)(Ps + r0 * PSD + c) = p0;
        *(float2*)(Ps + (r0 + 8) * PSD + c) = p1;
    }
    __syncthreads();

    /* ---- O = P V2 : warp grid 4x2 -> 16 rows x 32 dcols ---- */
    int dbase = wc * 32;
    float oa[4][4];
#pragma unroll
    for (int nt = 0; nt < 4; ++nt)
#pragma unroll
        for (int j = 0; j < 4; ++j) oa[nt][j] = 0.f;

#pragma unroll
    for (int ks = 0; ks < 16; ++ks) {
        int kbl = ks * 8 + lk;
        uint32_t a0 = __float_as_uint(Ps[r0 * PSD + kbl]);
        uint32_t a1 = __float_as_uint(Ps[(r0 + 8) * PSD + kbl]);
        uint32_t a2 = __float_as_uint(Ps[r0 * PSD + kbl + 4]);
        uint32_t a3 = __float_as_uint(Ps[(r0 + 8) * PSD + kbl + 4]);
#pragma unroll
        for (int nt = 0; nt < 4; ++nt) {
            int dcol = dbase + nt * 8 + g;
            uint32_t b0 = __float_as_uint(V2[kbl * KSV + dcol]);
            uint32_t b1 = __float_as_uint(V2[(kbl + 4) * KSV + dcol]);
            mma_tf32(oa[nt], a0, a1, a2, a3, b0, b1);
        }
    }

    /* store O with inverse head rotation */
    int tt0 = t0 + r0;
    int rt0 = rot ? ((tt0 + 63) & (T - 1)) : tt0;
    int tt1 = t0 + r0 + 8;
    int rt1 = rot ? ((tt1 + 63) & (T - 1)) : tt1;
    float* ob0 = out + ((size_t)bh * T + rt0) * DH;
    float* ob1 = out + ((size_t)bh * T + rt1) * DH;
#pragma unroll
    for (int nt = 0; nt < 4; ++nt) {
        int c = dbase + nt * 8 + 2 * lk;
        *(float2*)(ob0 + c) = make_float2(oa[nt][0], oa[nt][1]);
        *(float2*)(ob1 + c) = make_float2(oa[nt][2], oa[nt][3]);
    }
}

extern "C" void kernel_launch(void* const* d_in, const int* in_sizes, int n_in,
                              void* d_out, int out_size) {
    const float* q  = (const float*)d_in[0];
    const float* k  = (const float*)d_in[1];
    const float* v  = (const float*)d_in[2];
    const float* sW = (const float*)d_in[3];
    const float* nk = (const float*)d_in[4];
    const float* nv = (const float*)d_in[5];
    float* out = (float*)d_out;

    int smemB = (128 * 129 + 8 * 128) * 4;
    int smemC = SM_TOT * 4;                       /* 90112 B */
    cudaFuncSetAttribute(sc_stageB, cudaFuncAttributeMaxDynamicSharedMemorySize, smemB);
    cudaFuncSetAttribute(sc_stageC, cudaFuncAttributeMaxDynamicSharedMemorySize, smemC);

    sc_stageA1<<<dim3(BKT, BH), 256>>>(k);
    sc_stageA2<<<BH, DH>>>(k);
    sc_stageB<<<dim3(2, BH), 256, smemB>>>(sW);
    sc_stageC<<<dim3(BKT, BH), 256, smemC>>>(q, k, v, nk, nv, out);
}

// round 8
// speedup vs baseline: 2.5390x; 1.2231x over previous
#include <cuda_runtime.h>
#include <math.h>
#include <stdint.h>

#define B 8
#define H 8
#define T 8192
#define DH 64
#define BKT 128
#define BSZ 64
#define BH 64
#define HH 4
#define SCALE 0.04419417382415922f   /* (h*dh=512)^-0.5 */
#define NEG 3.402823466e38f
#define KSQ 68    /* Qs/K2 stride (floats) */
#define KSV 72    /* V2 stride */
#define PSD 132   /* Ps stride */

/* scratch (no allocation allowed) */
__device__ float g_ps[BH * BKT * DH];
__device__ int   g_idx[BH * BKT];
__device__ float g_w[BH * BKT];

__device__ __forceinline__ uint32_t f2tf32(float f) {
    uint32_t u;
    asm("cvt.rna.tf32.f32 %0, %1;" : "=r"(u) : "f"(f));
    return u;
}
__device__ __forceinline__ float tf32f(float f) {
    return __uint_as_float(f2tf32(f));
}
__device__ __forceinline__ void mma_tf32(float d[4], uint32_t a0, uint32_t a1,
                                         uint32_t a2, uint32_t a3,
                                         uint32_t b0, uint32_t b1) {
    asm("mma.sync.aligned.m16n8k8.row.col.f32.tf32.tf32.f32 "
        "{%0,%1,%2,%3}, {%4,%5,%6,%7}, {%8,%9}, {%0,%1,%2,%3};"
        : "+f"(d[0]), "+f"(d[1]), "+f"(d[2]), "+f"(d[3])
        : "r"(a0), "r"(a1), "r"(a2), "r"(a3), "r"(b0), "r"(b1));
}

/* ------------------------------------------------------------------ */
/* Stage A1: per-bucket sums of rotated K                              */
/* ------------------------------------------------------------------ */
__global__ void sc_stageA1(const float* __restrict__ k) {
    int u = blockIdx.x, bh = blockIdx.y;
    bool rot = (bh & 7) >= HH;
    __shared__ float P[4][DH];
    int tid = threadIdx.x;
    int d = tid & 63, part = tid >> 6;
    const float* kb = k + (size_t)bh * T * DH;
    int t0 = u * BSZ + part * 16;
    float s = 0.f;
#pragma unroll
    for (int j = 0; j < 16; ++j) {
        int tt = t0 + j;
        int rt = rot ? ((tt + 63) & (T - 1)) : tt;
        s += kb[(size_t)rt * DH + d];
    }
    P[part][d] = s;
    __syncthreads();
    if (part == 0)
        g_ps[((size_t)bh * BKT + u) * DH + d] = P[0][d] + P[1][d] + P[2][d] + P[3][d];
}

/* ------------------------------------------------------------------ */
/* Stage B: features (from g_ps) + sort-net logits -> top-1            */
/* grid (2, BH), 256 threads. smem: Ws[128*129] | xs[64*128]          */
/* ------------------------------------------------------------------ */
__global__ void sc_stageB(const float* __restrict__ sortW,
                          const float* __restrict__ k) {
    extern __shared__ float sm[];
    float* Ws = sm;                  /* 128*129 */
    float* xs = sm + 128 * 129;      /* 64*128  */
    int xblk = blockIdx.x;           /* 0/1: which half of buckets */
    int bh = blockIdx.y;
    int h = bh & 7;
    bool rot = h >= HH;
    int tid = threadIdx.x;           /* 256 */
    const float* Wh = sortW + (size_t)h * 128 * 129;
    for (int i = tid; i < 128 * 129; i += 256) Ws[i] = Wh[i];

    /* features for this block's 64 buckets */
    {
        int d = tid & 63, p = tid >> 6;          /* p: 0..3, 16 buckets each */
        const float* ps = g_ps + (size_t)bh * BKT * DH;
        const float* kb = k + (size_t)bh * T * DH;
        int ustart = xblk * 64 + p * 16;
        float base = 0.f;
        for (int u2 = 0; u2 < ustart; ++u2) base += ps[u2 * DH + d];
        for (int ul = p * 16; ul < p * 16 + 16; ++ul) {
            int ug = xblk * 64 + ul;
            int tt = ug * BSZ;
            int rt = rot ? ((tt + 63) & (T - 1)) : tt;
            float kf = kb[(size_t)rt * DH + d];
            xs[ul * 128 + d]      = (base + kf) / (float)(tt + 1);
            xs[ul * 128 + DH + d] = kf;
            base += ps[ug * DH + d];
        }
    }
    __syncthreads();

    int warp = tid >> 5, lane = tid & 31;
    for (int it = 0; it < 8; ++it) {
        int ul = it * 8 + warp;
        int u = xblk * 64 + ul;
        const float* xr = xs + ul * 128;
        float v[5];
#pragma unroll
        for (int g = 0; g < 5; ++g) {
            int c = lane + 32 * g;
            float acc = -NEG;
            if (c <= u) {
                float a = 0.f;
#pragma unroll 4
                for (int d = 0; d < 128; ++d) a += xr[d] * Ws[d * 129 + c];
                acc = a >= 0.f ? a : 0.01f * a;
            }
            v[g] = acc;
        }
        float m = v[0];
#pragma unroll
        for (int g = 1; g < 5; ++g) m = fmaxf(m, v[g]);
        for (int off = 16; off >= 1; off >>= 1)
            m = fmaxf(m, __shfl_xor_sync(0xffffffffu, m, off));
        float s = 0.f;
#pragma unroll
        for (int g = 0; g < 5; ++g) s += __expf(v[g] - m);
        for (int off = 16; off >= 1; off >>= 1)
            s += __shfl_xor_sync(0xffffffffu, s, off);
        float bv = -NEG; int bi = 0;
#pragma unroll
        for (int g = 0; g < 5; ++g) {
            int c = lane + 32 * g;
            if (c < u && v[g] > bv) { bv = v[g]; bi = c; }
        }
        for (int off = 16; off >= 1; off >>= 1) {
            float ov = __shfl_xor_sync(0xffffffffu, bv, off);
            int   oi = __shfl_xor_sync(0xffffffffu, bi, off);
            if (ov > bv || (ov == bv && oi < bi)) { bv = ov; bi = oi; }
        }
        if (lane == 0) {
            float w = 0.f; int idx = 0;
            if (u > 0 && bv > -NEG) { w = __expf(bv - m) / s; idx = bi; }
            g_w[bh * BKT + u]   = w;
            g_idx[bh * BKT + u] = idx;
        }
        __syncwarp();
    }
}

/* ------------------------------------------------------------------ */
/* Stage C: 64x128x64 attention tile, 128 threads, (2,2) warp grid    */
/* ------------------------------------------------------------------ */
#define SM_QS   0
#define SM_K2   (64 * KSQ)
#define SM_V2   (SM_K2 + 128 * KSQ)
#define SM_RED  (SM_V2 + 128 * KSV)
#define SM_TOT  (SM_RED + 256)

__global__ void __launch_bounds__(128, 2) sc_stageC(
    const float* __restrict__ q, const float* __restrict__ k,
    const float* __restrict__ v, const float* __restrict__ nk,
    const float* __restrict__ nv, float* __restrict__ out) {
    extern __shared__ float sm[];
    float* Qs = sm + SM_QS;
    float* K2 = sm + SM_K2;
    float* V2 = sm + SM_V2;
    float* Ps = sm + SM_K2;          /* overlay after S consumed */
    float* red = sm + SM_RED;

    int u = blockIdx.x, bh = blockIdx.y;
    int h = bh & 7;
    bool rot = h >= HH;
    int tid = threadIdx.x;           /* 128 */
    int t0 = u * BSZ;
    const float* qb = q + (size_t)bh * T * DH;
    const float* kb = k + (size_t)bh * T * DH;
    const float* vb = v + (size_t)bh * T * DH;

    int   ridx = g_idx[bh * BKT + u];
    float rw   = g_w[bh * BKT + u];

    /* cooperative load with tf32 conversion */
#pragma unroll
    for (int it = 0; it < 8; ++it) {
        int i = tid + 128 * it;
        int row = i >> 4, ch = i & 15;
        int tt = t0 + row;
        int rt = rot ? ((tt + 63) & (T - 1)) : tt;
        float4 q4 = *(const float4*)(qb + (size_t)rt * DH + ch * 4);
        Qs[row * KSQ + ch * 4 + 0] = tf32f(q4.x);
        Qs[row * KSQ + ch * 4 + 1] = tf32f(q4.y);
        Qs[row * KSQ + ch * 4 + 2] = tf32f(q4.z);
        Qs[row * KSQ + ch * 4 + 3] = tf32f(q4.w);
        float4 k4 = *(const float4*)(kb + (size_t)rt * DH + ch * 4);
        K2[(64 + row) * KSQ + ch * 4 + 0] = tf32f(k4.x);
        K2[(64 + row) * KSQ + ch * 4 + 1] = tf32f(k4.y);
        K2[(64 + row) * KSQ + ch * 4 + 2] = tf32f(k4.z);
        K2[(64 + row) * KSQ + ch * 4 + 3] = tf32f(k4.w);
        float4 v4 = *(const float4*)(vb + (size_t)rt * DH + ch * 4);
        V2[(64 + row) * KSV + ch * 4 + 0] = tf32f(v4.x);
        V2[(64 + row) * KSV + ch * 4 + 1] = tf32f(v4.y);
        V2[(64 + row) * KSV + ch * 4 + 2] = tf32f(v4.z);
        V2[(64 + row) * KSV + ch * 4 + 3] = tf32f(v4.w);
        float4 rk, rv;
        if (ridx == 0) {
            rk = *(const float4*)(nk + h * DH + ch * 4);
            rv = *(const float4*)(nv + h * DH + ch * 4);
        } else {
            int st = (ridx - 1) * BSZ + row;
            int srt = rot ? ((st + 63) & (T - 1)) : st;
            rk = *(const float4*)(kb + (size_t)srt * DH + ch * 4);
            rv = *(const float4*)(vb + (size_t)srt * DH + ch * 4);
        }
        K2[row * KSQ + ch * 4 + 0] = tf32f(rk.x * rw);
        K2[row * KSQ + ch * 4 + 1] = tf32f(rk.y * rw);
        K2[row * KSQ + ch * 4 + 2] = tf32f(rk.z * rw);
        K2[row * KSQ + ch * 4 + 3] = tf32f(rk.w * rw);
        V2[row * KSV + ch * 4 + 0] = tf32f(rv.x * rw);
        V2[row * KSV + ch * 4 + 1] = tf32f(rv.y * rw);
        V2[row * KSV + ch * 4 + 2] = tf32f(rv.z * rw);
        V2[row * KSV + ch * 4 + 3] = tf32f(rv.w * rw);
    }
    __syncthreads();

    int w  = tid >> 5, l = tid & 31;
    int wr = w & 1, wc = w >> 1;      /* 2x2 warp grid */
    int g  = l >> 2, lk = l & 3;
    int rbase = wr * 32;              /* 2 m16 tiles: rbase, rbase+16 */

    /* ---- S = Q K2^T : each warp 32 rows x 64 cols ---- */
    float sa[2][8][4];
#pragma unroll
    for (int t = 0; t < 2; ++t)
#pragma unroll
        for (int nt = 0; nt < 8; ++nt)
#pragma unroll
            for (int j = 0; j < 4; ++j) sa[t][nt][j] = 0.f;

#pragma unroll
    for (int ks = 0; ks < 8; ++ks) {
        int kc = ks * 8 + lk;
        uint32_t a[2][4];
#pragma unroll
        for (int t = 0; t < 2; ++t) {
            int r0 = rbase + t * 16 + g;
            a[t][0] = __float_as_uint(Qs[r0 * KSQ + kc]);
            a[t][1] = __float_as_uint(Qs[(r0 + 8) * KSQ + kc]);
            a[t][2] = __float_as_uint(Qs[r0 * KSQ + kc + 4]);
            a[t][3] = __float_as_uint(Qs[(r0 + 8) * KSQ + kc + 4]);
        }
#pragma unroll
        for (int nt = 0; nt < 8; ++nt) {
            int krow = wc * 64 + nt * 8 + g;
            uint32_t b0 = __float_as_uint(K2[krow * KSQ + kc]);
            uint32_t b1 = __float_as_uint(K2[krow * KSQ + kc + 4]);
#pragma unroll
            for (int t = 0; t < 2; ++t)
                mma_tf32(sa[t][nt], a[t][0], a[t][1], a[t][2], a[t][3], b0, b1);
        }
    }

    /* scale + mask */
    bool special = rot && (u == BKT - 1);
#pragma unroll
    for (int t = 0; t < 2; ++t) {
        int r0 = rbase + t * 16 + g;
#pragma unroll
        for (int nt = 0; nt < 8; ++nt) {
#pragma unroll
            for (int j = 0; j < 4; ++j) {
                int r = (j < 2) ? r0 : r0 + 8;
                int c = wc * 64 + nt * 8 + 2 * lk + (j & 1);
                bool ok = (c < BSZ) || (c - BSZ <= r);
                if (special && r >= 1 && c <= BSZ) ok = false;
                sa[t][nt][j] = ok ? sa[t][nt][j] * SCALE : -NEG;
            }
        }
    }

    /* row max: quad shfl + cross-warp (2 wc) via smem */
    float mx[2][2];
#pragma unroll
    for (int t = 0; t < 2; ++t) {
        float m0 = -NEG, m1 = -NEG;
#pragma unroll
        for (int nt = 0; nt < 8; ++nt) {
            m0 = fmaxf(m0, fmaxf(sa[t][nt][0], sa[t][nt][1]));
            m1 = fmaxf(m1, fmaxf(sa[t][nt][2], sa[t][nt][3]));
        }
#pragma unroll
        for (int off = 1; off <= 2; off <<= 1) {
            m0 = fmaxf(m0, __shfl_xor_sync(0xffffffffu, m0, off));
            m1 = fmaxf(m1, __shfl_xor_sync(0xffffffffu, m1, off));
        }
        mx[t][0] = m0; mx[t][1] = m1;
        if (lk == 0) {
            int r0 = rbase + t * 16 + g;
            red[r0 * 2 + wc] = m0;
            red[(r0 + 8) * 2 + wc] = m1;
        }
    }
    __syncthreads();
    float M[2][2];
#pragma unroll
    for (int t = 0; t < 2; ++t) {
        int r0 = rbase + t * 16 + g;
        M[t][0] = fmaxf(red[r0 * 2], red[r0 * 2 + 1]);
        M[t][1] = fmaxf(red[(r0 + 8) * 2], red[(r0 + 8) * 2 + 1]);
    }

    /* exp + row sums */
#pragma unroll
    for (int t = 0; t < 2; ++t) {
        float s0 = 0.f, s1 = 0.f;
#pragma unroll
        for (int nt = 0; nt < 8; ++nt) {
            sa[t][nt][0] = __expf(sa[t][nt][0] - M[t][0]); s0 += sa[t][nt][0];
            sa[t][nt][1] = __expf(sa[t][nt][1] - M[t][0]); s0 += sa[t][nt][1];
            sa[t][nt][2] = __expf(sa[t][nt][2] - M[t][1]); s1 += sa[t][nt][2];
            sa[t][nt][3] = __expf(sa[t][nt][3] - M[t][1]); s1 += sa[t][nt][3];
        }
#pragma unroll
        for (int off = 1; off <= 2; off <<= 1) {
            s0 += __shfl_xor_sync(0xffffffffu, s0, off);
            s1 += __shfl_xor_sync(0xffffffffu, s1, off);
        }
        if (lk == 0) {
            int r0 = rbase + t * 16 + g;
            red[128 + r0 * 2 + wc] = s0;
            red[128 + (r0 + 8) * 2 + wc] = s1;
        }
    }
    __syncthreads();

    /* write P (tf32) to overlay */
#pragma unroll
    for (int t = 0; t < 2; ++t) {
        int r0 = rbase + t * 16 + g;
        float inv0 = 1.f / (red[128 + r0 * 2] + red[128 + r0 * 2 + 1]);
        float inv1 = 1.f / (red[128 + (r0 + 8) * 2] + red[128 + (r0 + 8) * 2 + 1]);
#pragma unroll
        for (int nt = 0; nt < 8; ++nt) {
            int c = wc * 64 + nt * 8 + 2 * lk;
            *(float2*)(Ps + r0 * PSD + c) =
                make_float2(tf32f(sa[t][nt][0] * inv0), tf32f(sa[t][nt][1] * inv0));
            *(float2*)(Ps + (r0 + 8) * PSD + c) =
                make_float2(tf32f(sa[t][nt][2] * inv1), tf32f(sa[t][nt][3] * inv1));
        }
    }
    __syncthreads();

    /* ---- O = P V2 : each warp 32 rows x 32 dcols ---- */
    int dbase = wc * 32;
    float oa[2][4][4];
#pragma unroll
    for (int t = 0; t < 2; ++t)
#pragma unroll
        for (int nt = 0; nt < 4; ++nt)
#pragma unroll
            for (int j = 0; j < 4; ++j) oa[t][nt][j] = 0.f;

#pragma unroll
    for (int ks = 0; ks < 16; ++ks) {
        int kbl = ks * 8 + lk;
        uint32_t a[2][4];
#pragma unroll
        for (int t = 0; t < 2; ++t) {
            int r0 = rbase + t * 16 + g;
            a[t][0] = __float_as_uint(Ps[r0 * PSD + kbl]);
            a[t][1] = __float_as_uint(Ps[(r0 + 8) * PSD + kbl]);
            a[t][2] = __float_as_uint(Ps[r0 * PSD + kbl + 4]);
            a[t][3] = __float_as_uint(Ps[(r0 + 8) * PSD + kbl + 4]);
        }
#pragma unroll
        for (int nt = 0; nt < 4; ++nt) {
            int dcol = dbase + nt * 8 + g;
            uint32_t b0 = __float_as_uint(V2[kbl * KSV + dcol]);
            uint32_t b1 = __float_as_uint(V2[(kbl + 4) * KSV + dcol]);
#pragma unroll
            for (int t = 0; t < 2; ++t)
                mma_tf32(oa[t][nt], a[t][0], a[t][1], a[t][2], a[t][3], b0, b1);
        }
    }

    /* store O with inverse head rotation */
#pragma unroll
    for (int t = 0; t < 2; ++t) {
        int r0 = rbase + t * 16 + g;
        int tt0 = t0 + r0;
        int rt0 = rot ? ((tt0 + 63) & (T - 1)) : tt0;
        int tt1 = t0 + r0 + 8;
        int rt1 = rot ? ((tt1 + 63) & (T - 1)) : tt1;
        float* ob0 = out + ((size_t)bh * T + rt0) * DH;
        float* ob1 = out + ((size_t)bh * T + rt1) * DH;
#pragma unroll
        for (int nt = 0; nt < 4; ++nt) {
            int c = dbase + nt * 8 + 2 * lk;
            *(float2*)(ob0 + c) = make_float2(oa[t][nt][0], oa[t][nt][1]);
            *(float2*)(ob1 + c) = make_float2(oa[t][nt][2], oa[t][nt][3]);
        }
    }
}

extern "C" void kernel_launch(void* const* d_in, const int* in_sizes, int n_in,
                              void* d_out, int out_size) {
    const float* q  = (const float*)d_in[0];
    const float* k  = (const float*)d_in[1];
    const float* v  = (const float*)d_in[2];
    const float* sW = (const float*)d_in[3];
    const float* nk = (const float*)d_in[4];
    const float* nv = (const float*)d_in[5];
    float* out = (float*)d_out;

    int smemB = (128 * 129 + 64 * 128) * 4;       /* 98816 B */
    int smemC = SM_TOT * 4;                       /* 90112 B */
    cudaFuncSetAttribute(sc_stageB, cudaFuncAttributeMaxDynamicSharedMemorySize, smemB);
    cudaFuncSetAttribute(sc_stageC, cudaFuncAttributeMaxDynamicSharedMemorySize, smemC);

    sc_stageA1<<<dim3(BKT, BH), 256>>>(k);
    sc_stageB<<<dim3(2, BH), 256, smemB>>>(sW, k);
    sc_stageC<<<dim3(BKT, BH), 128, smemC>>>(q, k, v, nk, nv, out);
}

// round 10
// speedup vs baseline: 2.8360x; 1.1170x over previous
#include <cuda_runtime.h>
#include <math.h>
#include <stdint.h>

#define B 8
#define H 8
#define T 8192
#define DH 64
#define BKT 128
#define BSZ 64
#define BH 64
#define HH 4
#define SCALE 0.04419417382415922f   /* (h*dh=512)^-0.5 */
#define NEG 3.402823466e38f
#define KSQ 68    /* Qs/K2 stride (floats) */
#define KSV 72    /* V2 stride */
#define PSD 132   /* Ps stride */

/* scratch (no allocation allowed) */
__device__ float g_ps[BH * BKT * DH];
__device__ int   g_idx[BH * BKT];
__device__ float g_w[BH * BKT];

__device__ __forceinline__ uint32_t f2tf32(float f) {
    uint32_t u;
    asm("cvt.rna.tf32.f32 %0, %1;" : "=r"(u) : "f"(f));
    return u;
}
__device__ __forceinline__ float tf32f(float f) {
    return __uint_as_float(f2tf32(f));
}
__device__ __forceinline__ void mma_tf32(float d[4], uint32_t a0, uint32_t a1,
                                         uint32_t a2, uint32_t a3,
                                         uint32_t b0, uint32_t b1) {
    asm("mma.sync.aligned.m16n8k8.row.col.f32.tf32.tf32.f32 "
        "{%0,%1,%2,%3}, {%4,%5,%6,%7}, {%8,%9}, {%0,%1,%2,%3};"
        : "+f"(d[0]), "+f"(d[1]), "+f"(d[2]), "+f"(d[3])
        : "r"(a0), "r"(a1), "r"(a2), "r"(a3), "r"(b0), "r"(b1));
}

/* ------------------------------------------------------------------ */
/* Stage A1: per-bucket sums of rotated K                              */
/* ------------------------------------------------------------------ */
__global__ void sc_stageA1(const float* __restrict__ k) {
    int u = blockIdx.x, bh = blockIdx.y;
    bool rot = (bh & 7) >= HH;
    __shared__ float P[4][DH];
    int tid = threadIdx.x;
    int d = tid & 63, part = tid >> 6;
    const float* kb = k + (size_t)bh * T * DH;
    int t0 = u * BSZ + part * 16;
    float s = 0.f;
#pragma unroll
    for (int j = 0; j < 16; ++j) {
        int tt = t0 + j;
        int rt = rot ? ((tt + 63) & (T - 1)) : tt;
        s += kb[(size_t)rt * DH + d];
    }
    P[part][d] = s;
    __syncthreads();
    if (part == 0)
        g_ps[((size_t)bh * BKT + u) * DH + d] = P[0][d] + P[1][d] + P[2][d] + P[3][d];
}

/* ------------------------------------------------------------------ */
/* Stage B: features + sort-net logits -> top-1                        */
/* grid (4, BH), 256 threads, 32 buckets/block, 2 buckets per warp-it  */
/* smem: Ws[128*129] | xs[32*128]                                      */
/* ------------------------------------------------------------------ */
__global__ void sc_stageB(const float* __restrict__ sortW,
                          const float* __restrict__ k) {
    extern __shared__ float sm[];
    float* Ws = sm;                  /* 16512 */
    float* xs = sm + 128 * 129;      /* 32*128 = 4096 */
    int base = blockIdx.x * 32;
    int bh = blockIdx.y;
    int h = bh & 7;
    bool rot = h >= HH;
    int tid = threadIdx.x;           /* 256 */

    {   /* vectorized Ws fill: 16512 floats = 4128 float4 */
        const float4* Wh4 = (const float4*)(sortW + (size_t)h * 128 * 129);
        float4* Ws4 = (float4*)Ws;
        for (int i = tid; i < 4128; i += 256) Ws4[i] = Wh4[i];
    }

    /* features for this block's 32 buckets */
    {
        int d = tid & 63, p = tid >> 6;          /* p: 0..3, 8 buckets each */
        const float* ps = g_ps + (size_t)bh * BKT * DH;
        const float* kb = k + (size_t)bh * T * DH;
        int ustart = base + p * 8;
        float bacc = 0.f;
#pragma unroll 4
        for (int u2 = 0; u2 < ustart; ++u2) bacc += ps[u2 * DH + d];
        for (int ul = p * 8; ul < p * 8 + 8; ++ul) {
            int ug = base + ul;
            int tt = ug * BSZ;
            int rt = rot ? ((tt + 63) & (T - 1)) : tt;
            float kf = kb[(size_t)rt * DH + d];
            xs[ul * 128 + d]      = (bacc + kf) / (float)(tt + 1);
            xs[ul * 128 + DH + d] = kf;
            bacc += ps[ug * DH + d];
        }
    }
    __syncthreads();

    int warp = tid >> 5, lane = tid & 31;
#pragma unroll
    for (int it = 0; it < 2; ++it) {
        int pr = it * 8 + warp;                  /* pair 0..15 */
        int ua = base + 2 * pr, ub = ua + 1;
        const float* xa = xs + (2 * pr) * 128;
        const float* xb = xa + 128;
        int ng = (ub >> 5) + 1;                  /* groups with any c<=ub */
        if (ng > 4) ng = 4;

        float aa[4] = {0.f, 0.f, 0.f, 0.f};
        float ab[4] = {0.f, 0.f, 0.f, 0.f};
        for (int d = 0; d < 128; ++d) {
            float xav = xa[d];
            float xbv = xb[d];
            const float* wrow = Ws + d * 129 + lane;
#pragma unroll
            for (int g = 0; g < 4; ++g) {
                if (g < ng) {
                    float wv = wrow[32 * g];
                    aa[g] += xav * wv;
                    ab[g] += xbv * wv;
                }
            }
        }

        /* per-bucket epilogue: leaky+mask, softmax, argmax */
#pragma unroll
        for (int sel = 0; sel < 2; ++sel) {
            int u = sel ? ub : ua;
            float* ac = sel ? ab : aa;
            float v[4];
#pragma unroll
            for (int g = 0; g < 4; ++g) {
                int c = lane + 32 * g;
                float a = ac[g];
                v[g] = (c <= u) ? (a >= 0.f ? a : 0.01f * a) : -NEG;
            }
            float m = fmaxf(fmaxf(v[0], v[1]), fmaxf(v[2], v[3]));
            for (int off = 16; off >= 1; off >>= 1)
                m = fmaxf(m, __shfl_xor_sync(0xffffffffu, m, off));
            float s = 0.f;
#pragma unroll
            for (int g = 0; g < 4; ++g) s += __expf(v[g] - m);
            for (int off = 16; off >= 1; off >>= 1)
                s += __shfl_xor_sync(0xffffffffu, s, off);
            float bv = -NEG; int bi = 0;
#pragma unroll
            for (int g = 0; g < 4; ++g) {
                int c = lane + 32 * g;
                if (c < u && v[g] > bv) { bv = v[g]; bi = c; }
            }
            for (int off = 16; off >= 1; off >>= 1) {
                float ov = __shfl_xor_sync(0xffffffffu, bv, off);
                int   oi = __shfl_xor_sync(0xffffffffu, bi, off);
                if (ov > bv || (ov == bv && oi < bi)) { bv = ov; bi = oi; }
            }
            if (lane == 0) {
                float w = 0.f; int idx = 0;
                if (u > 0 && bv > -NEG) { w = __expf(bv - m) / s; idx = bi; }
                g_w[bh * BKT + u]   = w;
                g_idx[bh * BKT + u] = idx;
            }
        }
        __syncwarp();
    }
}

/* ------------------------------------------------------------------ */
/* Stage C: 64x128x64 attention tile, 128 threads, (2,2) warp grid,   */
/* phase-split smem -> 71.7 KB -> 3 CTAs/SM                           */
/* phase0: Qs[64][68] | K2[128][68]          (0 .. 13056)             */
/* phase1: Ps[64][132] (0..8448) | V2[128][72] (8448..17664)          */
/* red[256] at 17664                                                   */
/* ------------------------------------------------------------------ */
#define SM_K2   (64 * KSQ)          /* 4352 */
#define SM_V2   8448
#define SM_RED  17664
#define SM_TOT  17920

__global__ void __launch_bounds__(128, 3) sc_stageC(
    const float* __restrict__ q, const float* __restrict__ k,
    const float* __restrict__ v, const float* __restrict__ nk,
    const float* __restrict__ nv, float* __restrict__ out) {
    extern __shared__ float sm[];
    float* Qs = sm;
    float* K2 = sm + SM_K2;
    float* Ps = sm;                  /* overlay after S consumed */
    float* V2 = sm + SM_V2;          /* filled after S consumed  */
    float* red = sm + SM_RED;

    int u = blockIdx.x, bh = blockIdx.y;
    int h = bh & 7;
    bool rot = h >= HH;
    int tid = threadIdx.x;           /* 128 */
    int t0 = u * BSZ;
    const float* qb = q + (size_t)bh * T * DH;
    const float* kb = k + (size_t)bh * T * DH;
    const float* vb = v + (size_t)bh * T * DH;

    int   ridx = g_idx[bh * BKT + u];
    float rw   = g_w[bh * BKT + u];

    /* phase0 fill: Q, local K (rows 64..127), routed K * w (rows 0..63) */
#pragma unroll
    for (int it = 0; it < 8; ++it) {
        int i = tid + 128 * it;
        int row = i >> 4, ch = i & 15;
        int tt = t0 + row;
        int rt = rot ? ((tt + 63) & (T - 1)) : tt;
        float4 q4 = *(const float4*)(qb + (size_t)rt * DH + ch * 4);
        Qs[row * KSQ + ch * 4 + 0] = tf32f(q4.x);
        Qs[row * KSQ + ch * 4 + 1] = tf32f(q4.y);
        Qs[row * KSQ + ch * 4 + 2] = tf32f(q4.z);
        Qs[row * KSQ + ch * 4 + 3] = tf32f(q4.w);
        float4 k4 = *(const float4*)(kb + (size_t)rt * DH + ch * 4);
        K2[(64 + row) * KSQ + ch * 4 + 0] = tf32f(k4.x);
        K2[(64 + row) * KSQ + ch * 4 + 1] = tf32f(k4.y);
        K2[(64 + row) * KSQ + ch * 4 + 2] = tf32f(k4.z);
        K2[(64 + row) * KSQ + ch * 4 + 3] = tf32f(k4.w);
        float4 rk;
        if (ridx == 0) {
            rk = *(const float4*)(nk + h * DH + ch * 4);
        } else {
            int st = (ridx - 1) * BSZ + row;
            int srt = rot ? ((st + 63) & (T - 1)) : st;
            rk = *(const float4*)(kb + (size_t)srt * DH + ch * 4);
        }
        K2[row * KSQ + ch * 4 + 0] = tf32f(rk.x * rw);
        K2[row * KSQ + ch * 4 + 1] = tf32f(rk.y * rw);
        K2[row * KSQ + ch * 4 + 2] = tf32f(rk.z * rw);
        K2[row * KSQ + ch * 4 + 3] = tf32f(rk.w * rw);
    }
    __syncthreads();

    int w  = tid >> 5, l = tid & 31;
    int wr = w & 1, wc = w >> 1;      /* 2x2 warp grid */
    int g  = l >> 2, lk = l & 3;
    int rbase = wr * 32;

    /* ---- S = Q K2^T : each warp 32 rows x 64 cols ---- */
    float sa[2][8][4];
#pragma unroll
    for (int t = 0; t < 2; ++t)
#pragma unroll
        for (int nt = 0; nt < 8; ++nt)
#pragma unroll
            for (int j = 0; j < 4; ++j) sa[t][nt][j] = 0.f;

#pragma unroll
    for (int ks = 0; ks < 8; ++ks) {
        int kc = ks * 8 + lk;
        uint32_t a[2][4];
#pragma unroll
        for (int t = 0; t < 2; ++t) {
            int r0 = rbase + t * 16 + g;
            a[t][0] = __float_as_uint(Qs[r0 * KSQ + kc]);
            a[t][1] = __float_as_uint(Qs[(r0 + 8) * KSQ + kc]);
            a[t][2] = __float_as_uint(Qs[r0 * KSQ + kc + 4]);
            a[t][3] = __float_as_uint(Qs[(r0 + 8) * KSQ + kc + 4]);
        }
#pragma unroll
        for (int nt = 0; nt < 8; ++nt) {
            int krow = wc * 64 + nt * 8 + g;
            uint32_t b0 = __float_as_uint(K2[krow * KSQ + kc]);
            uint32_t b1 = __float_as_uint(K2[krow * KSQ + kc + 4]);
#pragma unroll
            for (int t = 0; t < 2; ++t)
                mma_tf32(sa[t][nt], a[t][0], a[t][1], a[t][2], a[t][3], b0, b1);
        }
    }

    /* scale + mask */
    bool special = rot && (u == BKT - 1);
#pragma unroll
    for (int t = 0; t < 2; ++t) {
        int r0 = rbase + t * 16 + g;
#pragma unroll
        for (int nt = 0; nt < 8; ++nt) {
#pragma unroll
            for (int j = 0; j < 4; ++j) {
                int r = (j < 2) ? r0 : r0 + 8;
                int c = wc * 64 + nt * 8 + 2 * lk + (j & 1);
                bool ok = (c < BSZ) || (c - BSZ <= r);
                if (special && r >= 1 && c <= BSZ) ok = false;
                sa[t][nt][j] = ok ? sa[t][nt][j] * SCALE : -NEG;
            }
        }
    }

    /* row max: quad shfl + cross-warp via smem (also fences S reads) */
#pragma unroll
    for (int t = 0; t < 2; ++t) {
        float m0 = -NEG, m1 = -NEG;
#pragma unroll
        for (int nt = 0; nt < 8; ++nt) {
            m0 = fmaxf(m0, fmaxf(sa[t][nt][0], sa[t][nt][1]));
            m1 = fmaxf(m1, fmaxf(sa[t][nt][2], sa[t][nt][3]));
        }
#pragma unroll
        for (int off = 1; off <= 2; off <<= 1) {
            m0 = fmaxf(m0, __shfl_xor_sync(0xffffffffu, m0, off));
            m1 = fmaxf(m1, __shfl_xor_sync(0xffffffffu, m1, off));
        }
        if (lk == 0) {
            int r0 = rbase + t * 16 + g;
            red[r0 * 2 + wc] = m0;
            red[(r0 + 8) * 2 + wc] = m1;
        }
    }
    __syncthreads();
    float M[2][2];
#pragma unroll
    for (int t = 0; t < 2; ++t) {
        int r0 = rbase + t * 16 + g;
        M[t][0] = fmaxf(red[r0 * 2], red[r0 * 2 + 1]);
        M[t][1] = fmaxf(red[(r0 + 8) * 2], red[(r0 + 8) * 2 + 1]);
    }

    /* exp + row sums */
#pragma unroll
    for (int t = 0; t < 2; ++t) {
        float s0 = 0.f, s1 = 0.f;
#pragma unroll
        for (int nt = 0; nt < 8; ++nt) {
            sa[t][nt][0] = __expf(sa[t][nt][0] - M[t][0]); s0 += sa[t][nt][0];
            sa[t][nt][1] = __expf(sa[t][nt][1] - M[t][0]); s0 += sa[t][nt][1];
            sa[t][nt][2] = __expf(sa[t][nt][2] - M[t][1]); s1 += sa[t][nt][2];
            sa[t][nt][3] = __expf(sa[t][nt][3] - M[t][1]); s1 += sa[t][nt][3];
        }
#pragma unroll
        for (int off = 1; off <= 2; off <<= 1) {
            s0 += __shfl_xor_sync(0xffffffffu, s0, off);
            s1 += __shfl_xor_sync(0xffffffffu, s1, off);
        }
        if (lk == 0) {
            int r0 = rbase + t * 16 + g;
            red[128 + r0 * 2 + wc] = s0;
            red[128 + (r0 + 8) * 2 + wc] = s1;
        }
    }
    __syncthreads();
    /* after this sync: Qs/K2 dead everywhere -> safe to overlay Ps/V2 */

    /* phase1 fill: V (rows 64..127), routed V * w (rows 0..63) */
#pragma unroll
    for (int it = 0; it < 8; ++it) {
        int i = tid + 128 * it;
        int row = i >> 4, ch = i & 15;
        int tt = t0 + row;
        int rt = rot ? ((tt + 63) & (T - 1)) : tt;
        float4 v4 = *(const float4*)(vb + (size_t)rt * DH + ch * 4);
        V2[(64 + row) * KSV + ch * 4 + 0] = tf32f(v4.x);
        V2[(64 + row) * KSV + ch * 4 + 1] = tf32f(v4.y);
        V2[(64 + row) * KSV + ch * 4 + 2] = tf32f(v4.z);
        V2[(64 + row) * KSV + ch * 4 + 3] = tf32f(v4.w);
        float4 rv;
        if (ridx == 0) {
            rv = *(const float4*)(nv + h * DH + ch * 4);
        } else {
            int st = (ridx - 1) * BSZ + row;
            int srt = rot ? ((st + 63) & (T - 1)) : st;
            rv = *(const float4*)(vb + (size_t)srt * DH + ch * 4);
        }
        V2[row * KSV + ch * 4 + 0] = tf32f(rv.x * rw);
        V2[row * KSV + ch * 4 + 1] = tf32f(rv.y * rw);
        V2[row * KSV + ch * 4 + 2] = tf32f(rv.z * rw);
        V2[row * KSV + ch * 4 + 3] = tf32f(rv.w * rw);
    }

    /* write P (tf32) to overlay */
#pragma unroll
    for (int t = 0; t < 2; ++t) {
        int r0 = rbase + t * 16 + g;
        float inv0 = 1.f / (red[128 + r0 * 2] + red[128 + r0 * 2 + 1]);
        float inv1 = 1.f / (red[128 + (r0 + 8) * 2] + red[128 + (r0 + 8) * 2 + 1]);
#pragma unroll
        for (int nt = 0; nt < 8; ++nt) {
            int c = wc * 64 + nt * 8 + 2 * lk;
            *(float2*)(Ps + r0 * PSD + c) =
                make_float2(tf32f(sa[t][nt][0] * inv0), tf32f(sa[t][nt][1] * inv0));
            *(float2*)(Ps + (r0 + 8) * PSD + c) =
                make_float2(tf32f(sa[t][nt][2] * inv1), tf32f(sa[t][nt][3] * inv1));
        }
    }
    __syncthreads();

    /* ---- O = P V2 : each warp 32 rows x 32 dcols ---- */
    int dbase = wc * 32;
    float oa[2][4][4];
#pragma unroll
    for (int t = 0; t < 2; ++t)
#pragma unroll
        for (int nt = 0; nt < 4; ++nt)
#pragma unroll
            for (int j = 0; j < 4; ++j) oa[t][nt][j] = 0.f;

#pragma unroll
    for (int ks = 0; ks < 16; ++ks) {
        int kbl = ks * 8 + lk;
        uint32_t a[2][4];
#pragma unroll
        for (int t = 0; t < 2; ++t) {
            int r0 = rbase + t * 16 + g;
            a[t][0] = __float_as_uint(Ps[r0 * PSD + kbl]);
            a[t][1] = __float_as_uint(Ps[(r0 + 8) * PSD + kbl]);
            a[t][2] = __float_as_uint(Ps[r0 * PSD + kbl + 4]);
            a[t][3] = __float_as_uint(Ps[(r0 + 8) * PSD + kbl + 4]);
        }
#pragma unroll
        for (int nt = 0; nt < 4; ++nt) {
            int dcol = dbase + nt * 8 + g;
            uint32_t b0 = __float_as_uint(V2[kbl * KSV + dcol]);
            uint32_t b1 = __float_as_uint(V2[(kbl + 4) * KSV + dcol]);
#pragma unroll
            for (int t = 0; t < 2; ++t)
                mma_tf32(oa[t][nt], a[t][0], a[t][1], a[t][2], a[t][3], b0, b1);
        }
    }

    /* store O with inverse head rotation */
#pragma unroll
    for (int t = 0; t < 2; ++t) {
        int r0 = rbase + t * 16 + g;
        int tt0 = t0 + r0;
        int rt0 = rot ? ((tt0 + 63) & (T - 1)) : tt0;
        int tt1 = t0 + r0 + 8;
        int rt1 = rot ? ((tt1 + 63) & (T - 1)) : tt1;
        float* ob0 = out + ((size_t)bh * T + rt0) * DH;
        float* ob1 = out + ((size_t)bh * T + rt1) * DH;
#pragma unroll
        for (int nt = 0; nt < 4; ++nt) {
            int c = dbase + nt * 8 + 2 * lk;
            *(float2*)(ob0 + c) = make_float2(oa[t][nt][0], oa[t][nt][1]);
            *(float2*)(ob1 + c) = make_float2(oa[t][nt][2], oa[t][nt][3]);
        }
    }
}

extern "C" void kernel_launch(void* const* d_in, const int* in_sizes, int n_in,
                              void* d_out, int out_size) {
    const float* q  = (const float*)d_in[0];
    const float* k  = (const float*)d_in[1];
    const float* v  = (const float*)d_in[2];
    const float* sW = (const float*)d_in[3];
    const float* nk = (const float*)d_in[4];
    const float* nv = (const float*)d_in[5];
    float* out = (float*)d_out;

    int smemB = (128 * 129 + 32 * 128) * 4;       /* 82432 B */
    int smemC = SM_TOT * 4;                       /* 71680 B */
    cudaFuncSetAttribute(sc_stageB, cudaFuncAttributeMaxDynamicSharedMemorySize, smemB);
    cudaFuncSetAttribute(sc_stageC, cudaFuncAttributeMaxDynamicSharedMemorySize, smemC);

    sc_stageA1<<<dim3(BKT, BH), 256>>>(k);
    sc_stageB<<<dim3(4, BH), 256, smemB>>>(sW, k);
    sc_stageC<<<dim3(BKT, BH), 128, smemC>>>(q, k, v, nk, nv, out);
}

// round 12
// speedup vs baseline: 3.8390x; 1.3537x over previous
#include <cuda_runtime.h>
#include <cuda_fp16.h>
#include <math.h>
#include <stdint.h>

#define B 8
#define H 8
#define T 8192
#define DH 64
#define BKT 128
#define BSZ 64
#define BH 64
#define HH 4
#define SCALE 0.04419417382415922f   /* (h*dh=512)^-0.5 */
#define NEG 3.402823466e38f
#define MASKV (-80.0f)

/* half-typed smem strides (in halves) */
#define QSH 72
#define K2H 72
#define PSH 136
#define V2H 72
/* byte offsets */
#define SMB_K2  9216
#define SMB_V2  17408
#define SMB_RED 35840
#define SMB_TOT 36352

/* scratch (no allocation allowed) */
__device__ float g_ps[BH * BKT * DH];
__device__ int   g_idx[BH * BKT];
__device__ float g_w[BH * BKT];

__device__ __forceinline__ uint32_t packh2(float a, float b) {
    __half2 h = __floats2half2_rn(a, b);
    return *(uint32_t*)&h;
}
__device__ __forceinline__ void mma_f16(float d[4], uint32_t a0, uint32_t a1,
                                        uint32_t a2, uint32_t a3,
                                        uint32_t b0, uint32_t b1) {
    asm("mma.sync.aligned.m16n8k16.row.col.f32.f16.f16.f32 "
        "{%0,%1,%2,%3}, {%4,%5,%6,%7}, {%8,%9}, {%0,%1,%2,%3};"
        : "+f"(d[0]), "+f"(d[1]), "+f"(d[2]), "+f"(d[3])
        : "r"(a0), "r"(a1), "r"(a2), "r"(a3), "r"(b0), "r"(b1));
}
__device__ __forceinline__ void ldsm_x2_t(uint32_t& r0, uint32_t& r1, uint32_t saddr) {
    asm volatile("ldmatrix.sync.aligned.m8n8.x2.trans.shared.b16 {%0,%1}, [%2];"
                 : "=r"(r0), "=r"(r1) : "r"(saddr));
}

/* ------------------------------------------------------------------ */
/* Stage A1: per-bucket sums of rotated K                              */
/* ------------------------------------------------------------------ */
__global__ void sc_stageA1(const float* __restrict__ k) {
    int u = blockIdx.x, bh = blockIdx.y;
    bool rot = (bh & 7) >= HH;
    __shared__ float P[4][DH];
    int tid = threadIdx.x;
    int d = tid & 63, part = tid >> 6;
    const float* kb = k + (size_t)bh * T * DH;
    int t0 = u * BSZ + part * 16;
    float s = 0.f;
#pragma unroll
    for (int j = 0; j < 16; ++j) {
        int tt = t0 + j;
        int rt = rot ? ((tt + 63) & (T - 1)) : tt;
        s += kb[(size_t)rt * DH + d];
    }
    P[part][d] = s;
    __syncthreads();
    if (part == 0)
        g_ps[((size_t)bh * BKT + u) * DH + d] = P[0][d] + P[1][d] + P[2][d] + P[3][d];
}

/* ------------------------------------------------------------------ */
/* Stage B: features + sort-net logits -> top-1                        */
/* ------------------------------------------------------------------ */
__global__ void sc_stageB(const float* __restrict__ sortW,
                          const float* __restrict__ k) {
    extern __shared__ float sm[];
    float* Ws = sm;                  /* 16512 */
    float* xs = sm + 128 * 129;      /* 32*128 */
    int base = blockIdx.x * 32;
    int bh = blockIdx.y;
    int h = bh & 7;
    bool rot = h >= HH;
    int tid = threadIdx.x;           /* 256 */

    {
        const float4* Wh4 = (const float4*)(sortW + (size_t)h * 128 * 129);
        float4* Ws4 = (float4*)Ws;
        for (int i = tid; i < 4128; i += 256) Ws4[i] = Wh4[i];
    }
    {
        int d = tid & 63, p = tid >> 6;
        const float* ps = g_ps + (size_t)bh * BKT * DH;
        const float* kb = k + (size_t)bh * T * DH;
        int ustart = base + p * 8;
        float bacc = 0.f;
#pragma unroll 4
        for (int u2 = 0; u2 < ustart; ++u2) bacc += ps[u2 * DH + d];
        for (int ul = p * 8; ul < p * 8 + 8; ++ul) {
            int ug = base + ul;
            int tt = ug * BSZ;
            int rt = rot ? ((tt + 63) & (T - 1)) : tt;
            float kf = kb[(size_t)rt * DH + d];
            xs[ul * 128 + d]      = (bacc + kf) / (float)(tt + 1);
            xs[ul * 128 + DH + d] = kf;
            bacc += ps[ug * DH + d];
        }
    }
    __syncthreads();

    int warp = tid >> 5, lane = tid & 31;
#pragma unroll
    for (int it = 0; it < 2; ++it) {
        int pr = it * 8 + warp;
        int ua = base + 2 * pr, ub = ua + 1;
        const float* xa = xs + (2 * pr) * 128;
        const float* xb = xa + 128;
        int ng = (ub >> 5) + 1;
        if (ng > 4) ng = 4;

        float aa[4] = {0.f, 0.f, 0.f, 0.f};
        float ab[4] = {0.f, 0.f, 0.f, 0.f};
        for (int d = 0; d < 128; ++d) {
            float xav = xa[d];
            float xbv = xb[d];
            const float* wrow = Ws + d * 129 + lane;
#pragma unroll
            for (int g = 0; g < 4; ++g) {
                if (g < ng) {
                    float wv = wrow[32 * g];
                    aa[g] += xav * wv;
                    ab[g] += xbv * wv;
                }
            }
        }
#pragma unroll
        for (int sel = 0; sel < 2; ++sel) {
            int u = sel ? ub : ua;
            float* ac = sel ? ab : aa;
            float v[4];
#pragma unroll
            for (int g = 0; g < 4; ++g) {
                int c = lane + 32 * g;
                float a = ac[g];
                v[g] = (c <= u) ? (a >= 0.f ? a : 0.01f * a) : -NEG;
            }
            float m = fmaxf(fmaxf(v[0], v[1]), fmaxf(v[2], v[3]));
            for (int off = 16; off >= 1; off >>= 1)
                m = fmaxf(m, __shfl_xor_sync(0xffffffffu, m, off));
            float s = 0.f;
#pragma unroll
            for (int g = 0; g < 4; ++g) s += __expf(v[g] - m);
            for (int off = 16; off >= 1; off >>= 1)
                s += __shfl_xor_sync(0xffffffffu, s, off);
            float bv = -NEG; int bi = 0;
#pragma unroll
            for (int g = 0; g < 4; ++g) {
                int c = lane + 32 * g;
                if (c < u && v[g] > bv) { bv = v[g]; bi = c; }
            }
            for (int off = 16; off >= 1; off >>= 1) {
                float ov = __shfl_xor_sync(0xffffffffu, bv, off);
                int   oi = __shfl_xor_sync(0xffffffffu, bi, off);
                if (ov > bv || (ov == bv && oi < bi)) { bv = ov; bi = oi; }
            }
            if (lane == 0) {
                float w = 0.f; int idx = 0;
                if (u > 0 && bv > -NEG) { w = __expf(bv - m) / s; idx = bi; }
                g_w[bh * BKT + u]   = w;
                g_idx[bh * BKT + u] = idx;
            }
        }
        __syncwarp();
    }
}

/* ------------------------------------------------------------------ */
/* Stage C: 64x128x64 attention via fp16 m16n8k16 MMA                 */
/* phase0: Qs half[64][72] | K2 half[128][72]   [0, 27648)            */
/* phase1: Ps half[64][136] [0,17408) | V2 half[128][72] [17408,35840)*/
/* red float[128] at 35840; total 36352 B -> 5 CTAs/SM                */
/* ------------------------------------------------------------------ */
__global__ void __launch_bounds__(128, 5) sc_stageC(
    const float* __restrict__ q, const float* __restrict__ k,
    const float* __restrict__ v, const float* __restrict__ nk,
    const float* __restrict__ nv, float* __restrict__ out) {
    extern __shared__ __align__(16) char smc[];
    __half* Qs = (__half*)smc;
    __half* K2 = (__half*)(smc + SMB_K2);
    __half* Ps = (__half*)smc;            /* overlay after S consumed */
    __half* V2 = (__half*)(smc + SMB_V2); /* filled after S consumed  */
    float* red = (float*)(smc + SMB_RED);

    int u = blockIdx.x, bh = blockIdx.y;
    int h = bh & 7;
    bool rot = h >= HH;
    int tid = threadIdx.x;           /* 128 */
    int t0 = u * BSZ;
    const float* qb = q + (size_t)bh * T * DH;
    const float* kb = k + (size_t)bh * T * DH;
    const float* vb = v + (size_t)bh * T * DH;

    int   ridx = g_idx[bh * BKT + u];
    float rw   = g_w[bh * BKT + u];

    /* phase0 fill: Q, local K (rows 64..127), routed K * w (rows 0..63) */
#pragma unroll
    for (int it = 0; it < 8; ++it) {
        int i = tid + 128 * it;
        int row = i >> 4, ch = i & 15;
        int tt = t0 + row;
        int rt = rot ? ((tt + 63) & (T - 1)) : tt;
        float4 q4 = *(const float4*)(qb + (size_t)rt * DH + ch * 4);
        *(uint2*)(Qs + row * QSH + ch * 4) =
            make_uint2(packh2(q4.x, q4.y), packh2(q4.z, q4.w));
        float4 k4 = *(const float4*)(kb + (size_t)rt * DH + ch * 4);
        *(uint2*)(K2 + (64 + row) * K2H + ch * 4) =
            make_uint2(packh2(k4.x, k4.y), packh2(k4.z, k4.w));
        float4 rk;
        if (ridx == 0) {
            rk = *(const float4*)(nk + h * DH + ch * 4);
        } else {
            int st = (ridx - 1) * BSZ + row;
            int srt = rot ? ((st + 63) & (T - 1)) : st;
            rk = *(const float4*)(kb + (size_t)srt * DH + ch * 4);
        }
        *(uint2*)(K2 + row * K2H + ch * 4) =
            make_uint2(packh2(rk.x * rw, rk.y * rw), packh2(rk.z * rw, rk.w * rw));
    }
    __syncthreads();

    int w  = tid >> 5, l = tid & 31;
    int wr = w & 1, wc = w >> 1;      /* 2x2 warp grid */
    int g  = l >> 2, lk = l & 3;
    int rbase = wr * 32;

    /* ---- S = Q K2^T : each warp 32 rows x 64 cols, k in 4 chunks of 16 ---- */
    float sa[2][8][4];
#pragma unroll
    for (int t = 0; t < 2; ++t)
#pragma unroll
        for (int nt = 0; nt < 8; ++nt)
#pragma unroll
            for (int j = 0; j < 4; ++j) sa[t][nt][j] = 0.f;

#pragma unroll
    for (int ck = 0; ck < 4; ++ck) {
        int kk = ck * 16;
        uint32_t a[2][4];
#pragma unroll
        for (int t = 0; t < 2; ++t) {
            int r0 = rbase + t * 16 + g;
            a[t][0] = *(const uint32_t*)(Qs + r0 * QSH + kk + 2 * lk);
            a[t][1] = *(const uint32_t*)(Qs + (r0 + 8) * QSH + kk + 2 * lk);
            a[t][2] = *(const uint32_t*)(Qs + r0 * QSH + kk + 2 * lk + 8);
            a[t][3] = *(const uint32_t*)(Qs + (r0 + 8) * QSH + kk + 2 * lk + 8);
        }
#pragma unroll
        for (int nt = 0; nt < 8; ++nt) {
            int krow = wc * 64 + nt * 8 + g;
            uint32_t b0 = *(const uint32_t*)(K2 + krow * K2H + kk + 2 * lk);
            uint32_t b1 = *(const uint32_t*)(K2 + krow * K2H + kk + 2 * lk + 8);
#pragma unroll
            for (int t = 0; t < 2; ++t)
                mma_f16(sa[t][nt], a[t][0], a[t][1], a[t][2], a[t][3], b0, b1);
        }
    }

    /* scale + mask + exp (no max subtraction: |logit| <~ 3 after scale) */
    bool special = rot && (u == BKT - 1);
#pragma unroll
    for (int t = 0; t < 2; ++t) {
        int r0 = rbase + t * 16 + g;
        float s0 = 0.f, s1 = 0.f;
#pragma unroll
        for (int nt = 0; nt < 8; ++nt) {
#pragma unroll
            for (int j = 0; j < 4; ++j) {
                int r = (j < 2) ? r0 : r0 + 8;
                int c = wc * 64 + nt * 8 + 2 * lk + (j & 1);
                bool ok = (c < BSZ) || (c - BSZ <= r);
                if (special && r >= 1 && c <= BSZ) ok = false;
                float p = __expf(ok ? sa[t][nt][j] * SCALE : MASKV);
                sa[t][nt][j] = p;
                if (j < 2) s0 += p; else s1 += p;
            }
        }
#pragma unroll
        for (int off = 1; off <= 2; off <<= 1) {
            s0 += __shfl_xor_sync(0xffffffffu, s0, off);
            s1 += __shfl_xor_sync(0xffffffffu, s1, off);
        }
        if (lk == 0) {
            red[r0 * 2 + wc] = s0;
            red[(r0 + 8) * 2 + wc] = s1;
        }
    }
    __syncthreads();
    /* Qs/K2 dead everywhere now */

    /* phase1 fill: V (rows 64..127), routed V * w (rows 0..63) */
#pragma unroll
    for (int it = 0; it < 8; ++it) {
        int i = tid + 128 * it;
        int row = i >> 4, ch = i & 15;
        int tt = t0 + row;
        int rt = rot ? ((tt + 63) & (T - 1)) : tt;
        float4 v4 = *(const float4*)(vb + (size_t)rt * DH + ch * 4);
        *(uint2*)(V2 + (64 + row) * V2H + ch * 4) =
            make_uint2(packh2(v4.x, v4.y), packh2(v4.z, v4.w));
        float4 rv;
        if (ridx == 0) {
            rv = *(const float4*)(nv + h * DH + ch * 4);
        } else {
            int st = (ridx - 1) * BSZ + row;
            int srt = rot ? ((st + 63) & (T - 1)) : st;
            rv = *(const float4*)(vb + (size_t)srt * DH + ch * 4);
        }
        *(uint2*)(V2 + row * V2H + ch * 4) =
            make_uint2(packh2(rv.x * rw, rv.y * rw), packh2(rv.z * rw, rv.w * rw));
    }

    /* write P (fp16) into overlay */
#pragma unroll
    for (int t = 0; t < 2; ++t) {
        int r0 = rbase + t * 16 + g;
        float inv0 = 1.f / (red[r0 * 2] + red[r0 * 2 + 1]);
        float inv1 = 1.f / (red[(r0 + 8) * 2] + red[(r0 + 8) * 2 + 1]);
#pragma unroll
        for (int nt = 0; nt < 8; ++nt) {
            int c = wc * 64 + nt * 8 + 2 * lk;
            *(uint32_t*)(Ps + r0 * PSH + c) =
                packh2(sa[t][nt][0] * inv0, sa[t][nt][1] * inv0);
            *(uint32_t*)(Ps + (r0 + 8) * PSH + c) =
                packh2(sa[t][nt][2] * inv1, sa[t][nt][3] * inv1);
        }
    }
    __syncthreads();

    /* ---- O = P V2 : each warp 32 rows x 32 dcols, k in 8 chunks of 16 ---- */
    int dbase = wc * 32;
    uint32_t v2s = (uint32_t)__cvta_generic_to_shared(V2);
    int lrow = l & 15;                /* ldmatrix row provider */
    float oa[2][4][4];
#pragma unroll
    for (int t = 0; t < 2; ++t)
#pragma unroll
        for (int nt = 0; nt < 4; ++nt)
#pragma unroll
            for (int j = 0; j < 4; ++j) oa[t][nt][j] = 0.f;

#pragma unroll
    for (int ck = 0; ck < 8; ++ck) {
        int kk = ck * 16;
        uint32_t a[2][4];
#pragma unroll
        for (int t = 0; t < 2; ++t) {
            int r0 = rbase + t * 16 + g;
            a[t][0] = *(const uint32_t*)(Ps + r0 * PSH + kk + 2 * lk);
            a[t][1] = *(const uint32_t*)(Ps + (r0 + 8) * PSH + kk + 2 * lk);
            a[t][2] = *(const uint32_t*)(Ps + r0 * PSH + kk + 2 * lk + 8);
            a[t][3] = *(const uint32_t*)(Ps + (r0 + 8) * PSH + kk + 2 * lk + 8);
        }
#pragma unroll
        for (int nt = 0; nt < 4; ++nt) {
            int dtile = dbase + nt * 8;
            uint32_t b0, b1;
            ldsm_x2_t(b0, b1, v2s + ((kk + lrow) * V2H + dtile) * 2);
#pragma unroll
            for (int t = 0; t < 2; ++t)
                mma_f16(oa[t][nt], a[t][0], a[t][1], a[t][2], a[t][3], b0, b1);
        }
    }

    /* store O with inverse head rotation */
#pragma unroll
    for (int t = 0; t < 2; ++t) {
        int r0 = rbase + t * 16 + g;
        int tt0 = t0 + r0;
        int rt0 = rot ? ((tt0 + 63) & (T - 1)) : tt0;
        int tt1 = t0 + r0 + 8;
        int rt1 = rot ? ((tt1 + 63) & (T - 1)) : tt1;
        float* ob0 = out + ((size_t)bh * T + rt0) * DH;
        float* ob1 = out + ((size_t)bh * T + rt1) * DH;
#pragma unroll
        for (int nt = 0; nt < 4; ++nt) {
            int c = dbase + nt * 8 + 2 * lk;
            *(float2*)(ob0 + c) = make_float2(oa[t][nt][0], oa[t][nt][1]);
            *(float2*)(ob1 + c) = make_float2(oa[t][nt][2], oa[t][nt][3]);
        }
    }
}

extern "C" void kernel_launch(void* const* d_in, const int* in_sizes, int n_in,
                              void* d_out, int out_size) {
    const float* q  = (const float*)d_in[0];
    const float* k  = (const float*)d_in[1];
    const float* v  = (const float*)d_in[2];
    const float* sW = (const float*)d_in[3];
    const float* nk = (const float*)d_in[4];
    const float* nv = (const float*)d_in[5];
    float* out = (float*)d_out;

    int smemB = (128 * 129 + 32 * 128) * 4;       /* 82432 B */
    int smemC = SMB_TOT;                          /* 36352 B */
    cudaFuncSetAttribute(sc_stageB, cudaFuncAttributeMaxDynamicSharedMemorySize, smemB);
    cudaFuncSetAttribute(sc_stageC, cudaFuncAttributeMaxDynamicSharedMemorySize, smemC);

    sc_stageA1<<<dim3(BKT, BH), 256>>>(k);
    sc_stageB<<<dim3(4, BH), 256, smemB>>>(sW, k);
    sc_stageC<<<dim3(BKT, BH), 128, smemC>>>(q, k, v, nk, nv, out);
}